// round 4
// baseline (speedup 1.0000x reference)
#include <cuda_runtime.h>
#include <math.h>

// ---------------- fixed problem shape ----------------
#define D_MODEL 1024
#define D_FF    4096
#define T_SEQ   4096
#define B_BATCH 4
#define N_TOK   (B_BATCH * T_SEQ)   // 16384 rows
#define H_HEADS 16
#define DK      64

// ---------------- device scratch (no cudaMalloc allowed) ----------------
__device__ float g_x1[(size_t)N_TOK * D_MODEL];
__device__ float g_q [(size_t)N_TOK * D_MODEL];
__device__ float g_k [(size_t)N_TOK * D_MODEL];
__device__ float g_v [(size_t)N_TOK * D_MODEL];
__device__ float g_os[(size_t)N_TOK * D_MODEL];
__device__ float g_o2[(size_t)N_TOK * D_MODEL];
__device__ float g_q2[(size_t)N_TOK * D_MODEL];
__device__ float g_h [(size_t)N_TOK * D_FF];
__device__ float g_y [(size_t)N_TOK * D_MODEL];

// ---------------- LayerNorm (optionally fused residual add) ----------------
// one block (256 threads) per row of 1024 floats
__global__ void __launch_bounds__(256) ln_kernel(
    const float* __restrict__ in, const float* __restrict__ res,
    const float* __restrict__ gam, const float* __restrict__ bet,
    float* __restrict__ out)
{
    const int row = blockIdx.x;
    const int tid = threadIdx.x;
    const size_t base = (size_t)row * D_MODEL;

    float4 v = *(const float4*)(in + base + tid * 4);
    if (res) {
        float4 r = *(const float4*)(res + base + tid * 4);
        v.x += r.x; v.y += r.y; v.z += r.z; v.w += r.w;
    }
    float s  = v.x + v.y + v.z + v.w;
    float ss = v.x * v.x + v.y * v.y + v.z * v.z + v.w * v.w;

    #pragma unroll
    for (int o = 16; o > 0; o >>= 1) {
        s  += __shfl_down_sync(0xffffffffu, s,  o);
        ss += __shfl_down_sync(0xffffffffu, ss, o);
    }
    __shared__ float sh_s[8], sh_ss[8];
    const int w = tid >> 5, l = tid & 31;
    if (l == 0) { sh_s[w] = s; sh_ss[w] = ss; }
    __syncthreads();
    if (tid == 0) {
        float ts = 0.f, tss = 0.f;
        #pragma unroll
        for (int i = 0; i < 8; i++) { ts += sh_s[i]; tss += sh_ss[i]; }
        sh_s[0] = ts; sh_ss[0] = tss;
    }
    __syncthreads();
    const float mu  = sh_s[0] * (1.0f / D_MODEL);
    const float var = sh_ss[0] * (1.0f / D_MODEL) - mu * mu;
    const float inv = rsqrtf(var + 1e-6f);

    float4 g4 = *(const float4*)(gam + tid * 4);
    float4 b4 = *(const float4*)(bet + tid * 4);
    float4 o4;
    o4.x = (v.x - mu) * inv * g4.x + b4.x;
    o4.y = (v.y - mu) * inv * g4.y + b4.y;
    o4.z = (v.z - mu) * inv * g4.z + b4.z;
    o4.w = (v.w - mu) * inv * g4.w + b4.w;
    *(float4*)(out + base + tid * 4) = o4;
}

// ---------------- per-token head-mixing attention ----------------
// attn[h,g] = softmax_g( q[h].k[g] / sqrt(64) ); o[h,d] = sum_g attn[h,g] v[g,d]
// output written in the "faithful head-major reshape" scrambled layout:
//   o_scr[b*T*D + h*T*DK + t*DK + d]
__global__ void __launch_bounds__(256) attn_kernel(
    const float* __restrict__ q, const float* __restrict__ k,
    const float* __restrict__ v, float* __restrict__ o_scr)
{
    const int row = blockIdx.x;       // b*T + t
    const int tid = threadIdx.x;      // 256
    __shared__ float sq[D_MODEL], sk[D_MODEL], sv[D_MODEL];
    __shared__ float sS[H_HEADS][H_HEADS + 1];

    const size_t base = (size_t)row * D_MODEL;
    ((float4*)sq)[tid] = *(const float4*)(q + base + tid * 4);
    ((float4*)sk)[tid] = *(const float4*)(k + base + tid * 4);
    ((float4*)sv)[tid] = *(const float4*)(v + base + tid * 4);
    __syncthreads();

    // scores: one (h,g) pair per thread
    {
        const int h = tid >> 4, g = tid & 15;
        float s = 0.f;
        #pragma unroll
        for (int d = 0; d < DK; d++) s += sq[h * DK + d] * sk[g * DK + d];
        sS[h][g] = s * 0.125f;   // 1/sqrt(64)
    }
    __syncthreads();

    // softmax over g, one head per thread (16 active)
    if (tid < H_HEADS) {
        float mx = -1e30f;
        #pragma unroll
        for (int g = 0; g < H_HEADS; g++) mx = fmaxf(mx, sS[tid][g]);
        float sum = 0.f;
        #pragma unroll
        for (int g = 0; g < H_HEADS; g++) {
            float e = expf(sS[tid][g] - mx);
            sS[tid][g] = e; sum += e;
        }
        const float invs = 1.0f / sum;
        #pragma unroll
        for (int g = 0; g < H_HEADS; g++) sS[tid][g] *= invs;
    }
    __syncthreads();

    // o[h,d] = sum_g P[h,g] * v[g,d]; write scrambled
    const int b = row / T_SEQ;
    const int t = row % T_SEQ;
    float* ob = o_scr + (size_t)b * T_SEQ * D_MODEL + (size_t)t * DK;
    #pragma unroll
    for (int i = 0; i < 4; i++) {
        const int idx = i * 256 + tid;
        const int h = idx >> 6, d = idx & 63;
        float acc = 0.f;
        #pragma unroll
        for (int g = 0; g < H_HEADS; g++) acc += sS[h][g] * sv[g * DK + d];
        ob[(size_t)h * T_SEQ * DK + d] = acc;
    }
}

// ---------------- fp32 SGEMM: C[M,Nn] = A[M,K] @ B[K,Nn] (+epilogue) --------
// BM=BN=128, BK=16, 256 threads, 8x8 per thread, float4 vectorized.
// EPI: 0 = none, 1 = bias + exact GELU, 2 = bias + residual add
template<int EPI>
__global__ void __launch_bounds__(256) sgemm_kernel(
    const float* __restrict__ A, const float* __restrict__ B,
    float* __restrict__ C, int K, int Nn,
    const float* __restrict__ bias, const float* __restrict__ res)
{
    __shared__ float As[16][128];
    __shared__ float Bs[16][128];

    const int tid = threadIdx.x;
    const int bm = blockIdx.y, bn = blockIdx.x;
    const float* Ab = A + (size_t)bm * 128 * K;
    const float* Bb = B + (size_t)bn * 128;

    const int tr = (tid >> 4) << 3;   // 0..120 row in tile
    const int tc = (tid & 15) << 3;   // 0..120 col in tile

    const int ar = tid >> 2;          // 0..63
    const int ac = (tid & 3) << 2;    // 0,4,8,12
    const int br = tid >> 5;          // 0..7
    const int bc = (tid & 31) << 2;   // 0..124

    float acc[8][8];
    #pragma unroll
    for (int i = 0; i < 8; i++)
        #pragma unroll
        for (int j = 0; j < 8; j++) acc[i][j] = 0.f;

    for (int k0 = 0; k0 < K; k0 += 16) {
        float4 a0 = *(const float4*)(Ab + (size_t)ar * K + k0 + ac);
        float4 a1 = *(const float4*)(Ab + (size_t)(ar + 64) * K + k0 + ac);
        float4 b0 = *(const float4*)(Bb + (size_t)(k0 + br) * Nn + bc);
        float4 b1 = *(const float4*)(Bb + (size_t)(k0 + br + 8) * Nn + bc);

        As[ac + 0][ar] = a0.x; As[ac + 1][ar] = a0.y;
        As[ac + 2][ar] = a0.z; As[ac + 3][ar] = a0.w;
        As[ac + 0][ar + 64] = a1.x; As[ac + 1][ar + 64] = a1.y;
        As[ac + 2][ar + 64] = a1.z; As[ac + 3][ar + 64] = a1.w;
        *(float4*)&Bs[br][bc]     = b0;
        *(float4*)&Bs[br + 8][bc] = b1;
        __syncthreads();

        #pragma unroll
        for (int kk = 0; kk < 16; kk++) {
            float4 ra0 = *(const float4*)&As[kk][tr];
            float4 ra1 = *(const float4*)&As[kk][tr + 4];
            float4 rb0 = *(const float4*)&Bs[kk][tc];
            float4 rb1 = *(const float4*)&Bs[kk][tc + 4];
            const float ra[8] = {ra0.x, ra0.y, ra0.z, ra0.w, ra1.x, ra1.y, ra1.z, ra1.w};
            const float rb[8] = {rb0.x, rb0.y, rb0.z, rb0.w, rb1.x, rb1.y, rb1.z, rb1.w};
            #pragma unroll
            for (int i = 0; i < 8; i++)
                #pragma unroll
                for (int j = 0; j < 8; j++)
                    acc[i][j] += ra[i] * rb[j];
        }
        __syncthreads();
    }

    const size_t rowBase = (size_t)bm * 128 + tr;
    const int    colBase = bn * 128 + tc;
    #pragma unroll
    for (int i = 0; i < 8; i++) {
        float o[8];
        #pragma unroll
        for (int j = 0; j < 8; j++) {
            float val = acc[i][j];
            if (EPI == 1) {
                val += bias[colBase + j];
                val = 0.5f * val * (1.0f + erff(val * 0.70710678118654752f));
            } else if (EPI == 2) {
                val += bias[colBase + j]
                     + res[(rowBase + i) * (size_t)Nn + colBase + j];
            }
            o[j] = val;
        }
        float* crow = C + (rowBase + i) * (size_t)Nn + colBase;
        *(float4*)(crow)     = make_float4(o[0], o[1], o[2], o[3]);
        *(float4*)(crow + 4) = make_float4(o[4], o[5], o[6], o[7]);
    }
}

// ---------------- launch ----------------
extern "C" void kernel_launch(void* const* d_in, const int* in_sizes, int n_in,
                              void* d_out, int out_size)
{
    const float* x     = (const float*)d_in[0];
    const float* wq    = (const float*)d_in[1];
    const float* wk    = (const float*)d_in[2];
    const float* wv    = (const float*)d_in[3];
    const float* wo    = (const float*)d_in[4];
    const float* ln1g  = (const float*)d_in[5];
    const float* ln1b  = (const float*)d_in[6];
    const float* w1    = (const float*)d_in[7];
    const float* b1    = (const float*)d_in[8];
    const float* w2    = (const float*)d_in[9];
    const float* b2    = (const float*)d_in[10];
    const float* ln2g  = (const float*)d_in[11];
    const float* ln2b  = (const float*)d_in[12];
    float* out = (float*)d_out;

    float *x1, *q, *k, *v, *os, *o2, *q2, *h, *y;
    cudaGetSymbolAddress((void**)&x1, g_x1);
    cudaGetSymbolAddress((void**)&q,  g_q);
    cudaGetSymbolAddress((void**)&k,  g_k);
    cudaGetSymbolAddress((void**)&v,  g_v);
    cudaGetSymbolAddress((void**)&os, g_os);
    cudaGetSymbolAddress((void**)&o2, g_o2);
    cudaGetSymbolAddress((void**)&q2, g_q2);
    cudaGetSymbolAddress((void**)&h,  g_h);
    cudaGetSymbolAddress((void**)&y,  g_y);

    const dim3 gD(D_MODEL / 128, N_TOK / 128);   // (8, 128)
    const dim3 gF(D_FF    / 128, N_TOK / 128);   // (32, 128)

    // 1) x1 = LN(x)
    ln_kernel<<<N_TOK, 256>>>(x, nullptr, ln1g, ln1b, x1);
    // 2) q,k,v = x1 @ {wq,wk,wv}
    sgemm_kernel<0><<<gD, 256>>>(x1, wq, q, D_MODEL, D_MODEL, nullptr, nullptr);
    sgemm_kernel<0><<<gD, 256>>>(x1, wk, k, D_MODEL, D_MODEL, nullptr, nullptr);
    sgemm_kernel<0><<<gD, 256>>>(x1, wv, v, D_MODEL, D_MODEL, nullptr, nullptr);
    // 3) per-token head-mix attention, scrambled output layout
    attn_kernel<<<N_TOK, 256>>>(q, k, v, os);
    // 4) o2 = o_scr @ wo
    sgemm_kernel<0><<<gD, 256>>>(os, wo, o2, D_MODEL, D_MODEL, nullptr, nullptr);
    // 5) q2 = LN(o2 + x) with ln1 params (faithful reuse)
    ln_kernel<<<N_TOK, 256>>>(o2, x, ln1g, ln1b, q2);
    // 6) h = gelu(q2 @ w1 + b1)
    sgemm_kernel<1><<<gF, 256>>>(q2, w1, h, D_MODEL, D_FF, b1, nullptr);
    // 7) y = h @ w2 + b2 + q2
    sgemm_kernel<2><<<gD, 256>>>(h, w2, y, D_FF, D_MODEL, b2, q2);
    // 8) out = LN(y) with ln2 params
    ln_kernel<<<N_TOK, 256>>>(y, nullptr, ln2g, ln2b, out);
}

// round 8
// speedup vs baseline: 2.2222x; 2.2222x over previous
#include <cuda_runtime.h>
#include <cuda_bf16.h>
#include <math.h>
#include <stdint.h>

#define D_MODEL 1024
#define D_FF    4096
#define T_SEQ   4096
#define N_TOK   16384
#define H_HEADS 16
#define DK      64

#define GEMM_SMEM 65536   // 2 stages x (Ah 8K | Al 8K | Bh 8K | Bl 8K)

// ---------------- device scratch ----------------
__device__ float g_q [(size_t)N_TOK * D_MODEL];
__device__ float g_k [(size_t)N_TOK * D_MODEL];
__device__ float g_v [(size_t)N_TOK * D_MODEL];
__device__ float g_o2[(size_t)N_TOK * D_MODEL];
__device__ float g_q2[(size_t)N_TOK * D_MODEL];
__device__ float g_y [(size_t)N_TOK * D_MODEL];

__device__ __align__(16) __nv_bfloat16 g_x1h[(size_t)N_TOK * D_MODEL];
__device__ __align__(16) __nv_bfloat16 g_x1l[(size_t)N_TOK * D_MODEL];
__device__ __align__(16) __nv_bfloat16 g_osh[(size_t)N_TOK * D_MODEL];
__device__ __align__(16) __nv_bfloat16 g_osl[(size_t)N_TOK * D_MODEL];
__device__ __align__(16) __nv_bfloat16 g_q2h[(size_t)N_TOK * D_MODEL];
__device__ __align__(16) __nv_bfloat16 g_q2l[(size_t)N_TOK * D_MODEL];
__device__ __align__(16) __nv_bfloat16 g_hh [(size_t)N_TOK * D_FF];
__device__ __align__(16) __nv_bfloat16 g_hl [(size_t)N_TOK * D_FF];
__device__ __align__(16) __nv_bfloat16 g_wqh[(size_t)D_MODEL * D_MODEL];
__device__ __align__(16) __nv_bfloat16 g_wql[(size_t)D_MODEL * D_MODEL];
__device__ __align__(16) __nv_bfloat16 g_wkh[(size_t)D_MODEL * D_MODEL];
__device__ __align__(16) __nv_bfloat16 g_wkl[(size_t)D_MODEL * D_MODEL];
__device__ __align__(16) __nv_bfloat16 g_wvh[(size_t)D_MODEL * D_MODEL];
__device__ __align__(16) __nv_bfloat16 g_wvl[(size_t)D_MODEL * D_MODEL];
__device__ __align__(16) __nv_bfloat16 g_woh[(size_t)D_MODEL * D_MODEL];
__device__ __align__(16) __nv_bfloat16 g_wol[(size_t)D_MODEL * D_MODEL];
__device__ __align__(16) __nv_bfloat16 g_w1h[(size_t)D_MODEL * D_FF];
__device__ __align__(16) __nv_bfloat16 g_w1l[(size_t)D_MODEL * D_FF];
__device__ __align__(16) __nv_bfloat16 g_w2h[(size_t)D_FF * D_MODEL];
__device__ __align__(16) __nv_bfloat16 g_w2l[(size_t)D_FF * D_MODEL];

// ---------------- helpers ----------------
__device__ __forceinline__ uint32_t smem_u32(const void* p) {
    uint32_t a;
    asm("{ .reg .u64 t; cvta.to.shared.u64 t, %1; cvt.u32.u64 %0, t; }" : "=r"(a) : "l"(p));
    return a;
}
__device__ __forceinline__ void ldsm_x4(uint32_t* r, uint32_t a) {
    asm volatile("ldmatrix.sync.aligned.m8n8.x4.shared.b16 {%0,%1,%2,%3}, [%4];"
                 : "=r"(r[0]), "=r"(r[1]), "=r"(r[2]), "=r"(r[3]) : "r"(a));
}
__device__ __forceinline__ void ldsm_x4t(uint32_t* r, uint32_t a) {
    asm volatile("ldmatrix.sync.aligned.m8n8.x4.trans.shared.b16 {%0,%1,%2,%3}, [%4];"
                 : "=r"(r[0]), "=r"(r[1]), "=r"(r[2]), "=r"(r[3]) : "r"(a));
}
__device__ __forceinline__ void mma16816(float* d, const uint32_t* a, uint32_t b0, uint32_t b1) {
    asm volatile("mma.sync.aligned.m16n8k16.row.col.f32.bf16.bf16.f32 "
                 "{%0,%1,%2,%3}, {%4,%5,%6,%7}, {%8,%9}, {%0,%1,%2,%3};"
                 : "+f"(d[0]), "+f"(d[1]), "+f"(d[2]), "+f"(d[3])
                 : "r"(a[0]), "r"(a[1]), "r"(a[2]), "r"(a[3]), "r"(b0), "r"(b1));
}
__device__ __forceinline__ void split2(float x, float y,
                                       __nv_bfloat162* h, __nv_bfloat162* l) {
    __nv_bfloat16 hx = __float2bfloat16_rn(x);
    __nv_bfloat16 hy = __float2bfloat16_rn(y);
    h->x = hx; h->y = hy;
    l->x = __float2bfloat16_rn(x - __bfloat162float(hx));
    l->y = __float2bfloat16_rn(y - __bfloat162float(hy));
}

// ---------------- fp32 -> bf16 hi/lo converter ----------------
__global__ void __launch_bounds__(256) conv_kernel(
    const float* __restrict__ W, __nv_bfloat16* __restrict__ Wh,
    __nv_bfloat16* __restrict__ Wl, int n4)
{
    int i = blockIdx.x * 256 + threadIdx.x;
    if (i >= n4) return;
    float4 v = ((const float4*)W)[i];
    __nv_bfloat162 h0, l0, h1, l1;
    split2(v.x, v.y, &h0, &l0);
    split2(v.z, v.w, &h1, &l1);
    ((__nv_bfloat162*)Wh)[2 * i]     = h0;
    ((__nv_bfloat162*)Wh)[2 * i + 1] = h1;
    ((__nv_bfloat162*)Wl)[2 * i]     = l0;
    ((__nv_bfloat162*)Wl)[2 * i + 1] = l1;
}

// ---------------- LayerNorm (+res), optional fp32 and bf16 hi/lo out -------
__global__ void __launch_bounds__(256) ln_kernel(
    const float* __restrict__ in, const float* __restrict__ res,
    const float* __restrict__ gam, const float* __restrict__ bet,
    float* __restrict__ outf, __nv_bfloat16* __restrict__ outh,
    __nv_bfloat16* __restrict__ outl)
{
    const int row = blockIdx.x, tid = threadIdx.x;
    const size_t base = (size_t)row * D_MODEL;
    float4 v = *(const float4*)(in + base + tid * 4);
    if (res) {
        float4 r = *(const float4*)(res + base + tid * 4);
        v.x += r.x; v.y += r.y; v.z += r.z; v.w += r.w;
    }
    float s  = v.x + v.y + v.z + v.w;
    float ss = v.x * v.x + v.y * v.y + v.z * v.z + v.w * v.w;
    #pragma unroll
    for (int o = 16; o > 0; o >>= 1) {
        s  += __shfl_down_sync(0xffffffffu, s,  o);
        ss += __shfl_down_sync(0xffffffffu, ss, o);
    }
    __shared__ float sh_s[8], sh_ss[8];
    const int w = tid >> 5, l = tid & 31;
    if (l == 0) { sh_s[w] = s; sh_ss[w] = ss; }
    __syncthreads();
    if (tid == 0) {
        float ts = 0.f, tss = 0.f;
        #pragma unroll
        for (int i = 0; i < 8; i++) { ts += sh_s[i]; tss += sh_ss[i]; }
        sh_s[0] = ts; sh_ss[0] = tss;
    }
    __syncthreads();
    const float mu  = sh_s[0] * (1.0f / D_MODEL);
    const float var = sh_ss[0] * (1.0f / D_MODEL) - mu * mu;
    const float inv = rsqrtf(var + 1e-6f);
    float4 g4 = *(const float4*)(gam + tid * 4);
    float4 b4 = *(const float4*)(bet + tid * 4);
    float4 o4;
    o4.x = (v.x - mu) * inv * g4.x + b4.x;
    o4.y = (v.y - mu) * inv * g4.y + b4.y;
    o4.z = (v.z - mu) * inv * g4.z + b4.z;
    o4.w = (v.w - mu) * inv * g4.w + b4.w;
    if (outf) *(float4*)(outf + base + tid * 4) = o4;
    if (outh) {
        __nv_bfloat162 h0, l0, h1, l1;
        split2(o4.x, o4.y, &h0, &l0);
        split2(o4.z, o4.w, &h1, &l1);
        *(__nv_bfloat162*)(outh + base + tid * 4)     = h0;
        *(__nv_bfloat162*)(outh + base + tid * 4 + 2) = h1;
        *(__nv_bfloat162*)(outl + base + tid * 4)     = l0;
        *(__nv_bfloat162*)(outl + base + tid * 4 + 2) = l1;
    }
}

// ---------------- per-token head-mixing attention (bf16 hi/lo out) --------
__global__ void __launch_bounds__(256) attn_kernel(
    const float* __restrict__ q, const float* __restrict__ k,
    const float* __restrict__ v, __nv_bfloat16* __restrict__ oh,
    __nv_bfloat16* __restrict__ ol)
{
    const int row = blockIdx.x, tid = threadIdx.x;
    __shared__ float sq[D_MODEL], sk[D_MODEL], sv[D_MODEL];
    __shared__ float sS[H_HEADS][H_HEADS + 1];
    const size_t base = (size_t)row * D_MODEL;
    ((float4*)sq)[tid] = *(const float4*)(q + base + tid * 4);
    ((float4*)sk)[tid] = *(const float4*)(k + base + tid * 4);
    ((float4*)sv)[tid] = *(const float4*)(v + base + tid * 4);
    __syncthreads();
    {
        const int h = tid >> 4, g = tid & 15;
        float s = 0.f;
        #pragma unroll
        for (int d = 0; d < DK; d++) s += sq[h * DK + d] * sk[g * DK + d];
        sS[h][g] = s * 0.125f;
    }
    __syncthreads();
    if (tid < H_HEADS) {
        float mx = -1e30f;
        #pragma unroll
        for (int g = 0; g < H_HEADS; g++) mx = fmaxf(mx, sS[tid][g]);
        float sum = 0.f;
        #pragma unroll
        for (int g = 0; g < H_HEADS; g++) {
            float e = expf(sS[tid][g] - mx);
            sS[tid][g] = e; sum += e;
        }
        const float invs = 1.0f / sum;
        #pragma unroll
        for (int g = 0; g < H_HEADS; g++) sS[tid][g] *= invs;
    }
    __syncthreads();
    const int b = row / T_SEQ, t = row % T_SEQ;
    const size_t ob = (size_t)b * T_SEQ * D_MODEL + (size_t)t * DK;
    #pragma unroll
    for (int i = 0; i < 4; i++) {
        const int idx = i * 256 + tid;
        const int h = idx >> 6, d = idx & 63;
        float acc = 0.f;
        #pragma unroll
        for (int g = 0; g < H_HEADS; g++) acc += sS[h][g] * sv[g * DK + d];
        const size_t off = ob + (size_t)h * T_SEQ * DK + d;
        __nv_bfloat16 hi = __float2bfloat16_rn(acc);
        oh[off] = hi;
        ol[off] = __float2bfloat16_rn(acc - __bfloat162float(hi));
    }
}

// ---------------- bf16 3-product HMMA GEMM ----------------
// C[M,Nn] = (Ah+Al)[M,K] @ (Bh+Bl)[K,Nn], fp32 acc, 3 products.
// EPI: 0 fp32 out; 1 bias+GELU -> bf16 hi/lo out; 2 bias+res -> fp32 out
template<int EPI>
__global__ void __launch_bounds__(256) hmma_gemm(
    const __nv_bfloat16* __restrict__ Ah, const __nv_bfloat16* __restrict__ Al,
    const __nv_bfloat16* __restrict__ Bh, const __nv_bfloat16* __restrict__ Bl,
    float* __restrict__ C, __nv_bfloat16* __restrict__ Ch, __nv_bfloat16* __restrict__ Cl,
    int K, int Nn, const float* __restrict__ bias, const float* __restrict__ res)
{
    extern __shared__ __align__(16) char sm[];
    const int tid = threadIdx.x, lane = tid & 31, wid = tid >> 5;
    const int bm = blockIdx.y, bn = blockIdx.x;
    const int wm = (wid >> 2) * 64, wn = (wid & 3) * 32;
    const uint32_t sb0 = smem_u32(sm);

    const int rA0 = tid >> 2, cA0 = tid & 3;     // A chunks: rows rA0, rA0+64
    const int rB0 = tid >> 4, cB0 = tid & 15;    // B chunks: rows rB0, rB0+16

    float acc[4][4][4];
    #pragma unroll
    for (int t = 0; t < 4; t++)
        #pragma unroll
        for (int vv = 0; vv < 4; vv++)
            #pragma unroll
            for (int e = 0; e < 4; e++) acc[t][vv][e] = 0.f;

    uint4 sAh[2], sAl[2], sBh[2], sBl[2];
    const int NK = K / 32;

    auto ldg = [&](int i) {
        const int k0 = i * 32;
        #pragma unroll
        for (int j = 0; j < 2; j++) {
            const int ra = rA0 + j * 64;
            const size_t oA = (size_t)(bm * 128 + ra) * K + k0 + cA0 * 8;
            sAh[j] = *(const uint4*)(Ah + oA);
            sAl[j] = *(const uint4*)(Al + oA);
            const int rb = rB0 + j * 16;
            const size_t oB = (size_t)(k0 + rb) * Nn + bn * 128 + cB0 * 8;
            sBh[j] = *(const uint4*)(Bh + oB);
            sBl[j] = *(const uint4*)(Bl + oB);
        }
    };
    auto sts = [&](int s) {
        char* base = sm + s * 32768;
        #pragma unroll
        for (int j = 0; j < 2; j++) {
            const int ra = rA0 + j * 64;
            const int offA = ra * 64 + ((cA0 ^ ((ra >> 1) & 3)) << 4);
            *(uint4*)(base + offA)        = sAh[j];
            *(uint4*)(base + 8192 + offA) = sAl[j];
            const int rb = rB0 + j * 16;
            const int offB = rb * 256 + ((cB0 ^ (rb & 7)) << 4);
            *(uint4*)(base + 16384 + offB) = sBh[j];
            *(uint4*)(base + 24576 + offB) = sBl[j];
        }
    };
    auto tile = [&](int s) {
        const uint32_t sb = sb0 + s * 32768;
        #pragma unroll
        for (int kk = 0; kk < 32; kk += 16) {
            uint32_t ah[4][4], al[4][4], bh[2][4], bl[2][4];
            const int acol = (kk >> 3) + ((lane >> 4) & 1);
            #pragma unroll
            for (int t = 0; t < 4; t++) {
                const int r = wm + t * 16 + (lane & 15);
                const uint32_t ad = sb + r * 64 + ((acol ^ ((r >> 1) & 3)) << 4);
                ldsm_x4(ah[t], ad);
                ldsm_x4(al[t], ad + 8192);
            }
            const int rk = kk + (lane & 15);
            #pragma unroll
            for (int u = 0; u < 2; u++) {
                const int cB = (wn + u * 16 + ((lane & 16) ? 8 : 0)) >> 3;
                const uint32_t bd = sb + 16384 + rk * 256 + ((cB ^ (rk & 7)) << 4);
                ldsm_x4t(bh[u], bd);
                ldsm_x4t(bl[u], bd + 8192);
            }
            #pragma unroll
            for (int t = 0; t < 4; t++)
                #pragma unroll
                for (int vv = 0; vv < 4; vv++) {
                    const int u = vv >> 1, e = (vv & 1) * 2;
                    mma16816(acc[t][vv], ah[t], bh[u][e], bh[u][e + 1]);
                    mma16816(acc[t][vv], ah[t], bl[u][e], bl[u][e + 1]);
                    mma16816(acc[t][vv], al[t], bh[u][e], bh[u][e + 1]);
                }
        }
    };

    ldg(0);
    sts(0);
    __syncthreads();
    for (int i = 0; i < NK; i++) {
        if (i + 1 < NK) ldg(i + 1);
        tile(i & 1);
        __syncthreads();
        if (i + 1 < NK) { sts((i + 1) & 1); __syncthreads(); }
    }

    // epilogue
    const int l4 = lane >> 2, l2 = (lane & 3) * 2;
    #pragma unroll
    for (int t = 0; t < 4; t++)
        #pragma unroll
        for (int vv = 0; vv < 4; vv++) {
            const int r0 = bm * 128 + wm + t * 16 + l4;
            const int c0 = bn * 128 + wn + vv * 8 + l2;
            #pragma unroll
            for (int half = 0; half < 2; half++) {
                const int r = r0 + half * 8;
                float v0 = acc[t][vv][half * 2];
                float v1 = acc[t][vv][half * 2 + 1];
                if (EPI == 1) {
                    v0 += bias[c0];     v1 += bias[c0 + 1];
                    v0 = 0.5f * v0 * (1.0f + erff(v0 * 0.70710678118654752f));
                    v1 = 0.5f * v1 * (1.0f + erff(v1 * 0.70710678118654752f));
                    __nv_bfloat162 h2, l2b;
                    split2(v0, v1, &h2, &l2b);
                    *(__nv_bfloat162*)(Ch + (size_t)r * Nn + c0) = h2;
                    *(__nv_bfloat162*)(Cl + (size_t)r * Nn + c0) = l2b;
                } else {
                    if (EPI == 2) {
                        float2 rr = *(const float2*)(res + (size_t)r * Nn + c0);
                        v0 += bias[c0] + rr.x;
                        v1 += bias[c0 + 1] + rr.y;
                    }
                    *(float2*)(C + (size_t)r * Nn + c0) = make_float2(v0, v1);
                }
            }
        }
}

// ---------------- launch ----------------
extern "C" void kernel_launch(void* const* d_in, const int* in_sizes, int n_in,
                              void* d_out, int out_size)
{
    const float* x     = (const float*)d_in[0];
    const float* wq    = (const float*)d_in[1];
    const float* wk    = (const float*)d_in[2];
    const float* wv    = (const float*)d_in[3];
    const float* wo    = (const float*)d_in[4];
    const float* ln1g  = (const float*)d_in[5];
    const float* ln1b  = (const float*)d_in[6];
    const float* w1    = (const float*)d_in[7];
    const float* b1    = (const float*)d_in[8];
    const float* w2    = (const float*)d_in[9];
    const float* b2    = (const float*)d_in[10];
    const float* ln2g  = (const float*)d_in[11];
    const float* ln2b  = (const float*)d_in[12];
    float* out = (float*)d_out;

    float *q, *k, *v, *o2, *q2, *y;
    __nv_bfloat16 *x1h, *x1l, *osh, *osl, *q2h, *q2l, *hh, *hl;
    __nv_bfloat16 *wqh, *wql, *wkh, *wkl, *wvh, *wvl, *woh, *wol, *w1h, *w1l, *w2h, *w2l;
    cudaGetSymbolAddress((void**)&q,  g_q);
    cudaGetSymbolAddress((void**)&k,  g_k);
    cudaGetSymbolAddress((void**)&v,  g_v);
    cudaGetSymbolAddress((void**)&o2, g_o2);
    cudaGetSymbolAddress((void**)&q2, g_q2);
    cudaGetSymbolAddress((void**)&y,  g_y);
    cudaGetSymbolAddress((void**)&x1h, g_x1h);
    cudaGetSymbolAddress((void**)&x1l, g_x1l);
    cudaGetSymbolAddress((void**)&osh, g_osh);
    cudaGetSymbolAddress((void**)&osl, g_osl);
    cudaGetSymbolAddress((void**)&q2h, g_q2h);
    cudaGetSymbolAddress((void**)&q2l, g_q2l);
    cudaGetSymbolAddress((void**)&hh,  g_hh);
    cudaGetSymbolAddress((void**)&hl,  g_hl);
    cudaGetSymbolAddress((void**)&wqh, g_wqh);
    cudaGetSymbolAddress((void**)&wql, g_wql);
    cudaGetSymbolAddress((void**)&wkh, g_wkh);
    cudaGetSymbolAddress((void**)&wkl, g_wkl);
    cudaGetSymbolAddress((void**)&wvh, g_wvh);
    cudaGetSymbolAddress((void**)&wvl, g_wvl);
    cudaGetSymbolAddress((void**)&woh, g_woh);
    cudaGetSymbolAddress((void**)&wol, g_wol);
    cudaGetSymbolAddress((void**)&w1h, g_w1h);
    cudaGetSymbolAddress((void**)&w1l, g_w1l);
    cudaGetSymbolAddress((void**)&w2h, g_w2h);
    cudaGetSymbolAddress((void**)&w2l, g_w2l);

    cudaFuncSetAttribute(hmma_gemm<0>, cudaFuncAttributeMaxDynamicSharedMemorySize, GEMM_SMEM);
    cudaFuncSetAttribute(hmma_gemm<1>, cudaFuncAttributeMaxDynamicSharedMemorySize, GEMM_SMEM);
    cudaFuncSetAttribute(hmma_gemm<2>, cudaFuncAttributeMaxDynamicSharedMemorySize, GEMM_SMEM);

    const int nDD4 = D_MODEL * D_MODEL / 4;      // 262144
    const int nDF4 = D_MODEL * D_FF / 4;         // 1048576
    conv_kernel<<<nDD4 / 256, 256>>>(wq, wqh, wql, nDD4);
    conv_kernel<<<nDD4 / 256, 256>>>(wk, wkh, wkl, nDD4);
    conv_kernel<<<nDD4 / 256, 256>>>(wv, wvh, wvl, nDD4);
    conv_kernel<<<nDD4 / 256, 256>>>(wo, woh, wol, nDD4);
    conv_kernel<<<nDF4 / 256, 256>>>(w1, w1h, w1l, nDF4);
    conv_kernel<<<nDF4 / 256, 256>>>(w2, w2h, w2l, nDF4);

    const dim3 gD(D_MODEL / 128, N_TOK / 128);   // (8, 128)
    const dim3 gF(D_FF    / 128, N_TOK / 128);   // (32, 128)

    ln_kernel<<<N_TOK, 256>>>(x, nullptr, ln1g, ln1b, nullptr, x1h, x1l);
    hmma_gemm<0><<<gD, 256, GEMM_SMEM>>>(x1h, x1l, wqh, wql, q, nullptr, nullptr,
                                         D_MODEL, D_MODEL, nullptr, nullptr);
    hmma_gemm<0><<<gD, 256, GEMM_SMEM>>>(x1h, x1l, wkh, wkl, k, nullptr, nullptr,
                                         D_MODEL, D_MODEL, nullptr, nullptr);
    hmma_gemm<0><<<gD, 256, GEMM_SMEM>>>(x1h, x1l, wvh, wvl, v, nullptr, nullptr,
                                         D_MODEL, D_MODEL, nullptr, nullptr);
    attn_kernel<<<N_TOK, 256>>>(q, k, v, osh, osl);
    hmma_gemm<0><<<gD, 256, GEMM_SMEM>>>(osh, osl, woh, wol, o2, nullptr, nullptr,
                                         D_MODEL, D_MODEL, nullptr, nullptr);
    ln_kernel<<<N_TOK, 256>>>(o2, x, ln1g, ln1b, q2, q2h, q2l);
    hmma_gemm<1><<<gF, 256, GEMM_SMEM>>>(q2h, q2l, w1h, w1l, nullptr, hh, hl,
                                         D_MODEL, D_FF, b1, nullptr);
    hmma_gemm<2><<<gD, 256, GEMM_SMEM>>>(hh, hl, w2h, w2l, y, nullptr, nullptr,
                                         D_FF, D_MODEL, b2, q2);
    ln_kernel<<<N_TOK, 256>>>(y, nullptr, ln2g, ln2b, out, nullptr, nullptr);
}

// round 9
// speedup vs baseline: 2.5383x; 1.1422x over previous
#include <cuda_runtime.h>
#include <cuda_bf16.h>
#include <math.h>
#include <stdint.h>

#define D_MODEL 1024
#define D_FF    4096
#define T_SEQ   4096
#define N_TOK   16384
#define H_HEADS 16
#define DK      64

#define STAGE_B   49152              // Ah 8K | Al 8K | Bh 16K | Bl 16K
#define GEMM_SMEM (3 * STAGE_B)      // 144 KB, 3-stage pipeline

// ---------------- device scratch ----------------
__device__ float g_q [(size_t)N_TOK * D_MODEL];
__device__ float g_k [(size_t)N_TOK * D_MODEL];
__device__ float g_v [(size_t)N_TOK * D_MODEL];
__device__ float g_o2[(size_t)N_TOK * D_MODEL];
__device__ float g_q2[(size_t)N_TOK * D_MODEL];
__device__ float g_y [(size_t)N_TOK * D_MODEL];

__device__ __align__(16) __nv_bfloat16 g_x1h[(size_t)N_TOK * D_MODEL];
__device__ __align__(16) __nv_bfloat16 g_x1l[(size_t)N_TOK * D_MODEL];
__device__ __align__(16) __nv_bfloat16 g_osh[(size_t)N_TOK * D_MODEL];
__device__ __align__(16) __nv_bfloat16 g_osl[(size_t)N_TOK * D_MODEL];
__device__ __align__(16) __nv_bfloat16 g_q2h[(size_t)N_TOK * D_MODEL];
__device__ __align__(16) __nv_bfloat16 g_q2l[(size_t)N_TOK * D_MODEL];
__device__ __align__(16) __nv_bfloat16 g_hh [(size_t)N_TOK * D_FF];
__device__ __align__(16) __nv_bfloat16 g_hl [(size_t)N_TOK * D_FF];
__device__ __align__(16) __nv_bfloat16 g_wqh[(size_t)D_MODEL * D_MODEL];
__device__ __align__(16) __nv_bfloat16 g_wql[(size_t)D_MODEL * D_MODEL];
__device__ __align__(16) __nv_bfloat16 g_wkh[(size_t)D_MODEL * D_MODEL];
__device__ __align__(16) __nv_bfloat16 g_wkl[(size_t)D_MODEL * D_MODEL];
__device__ __align__(16) __nv_bfloat16 g_wvh[(size_t)D_MODEL * D_MODEL];
__device__ __align__(16) __nv_bfloat16 g_wvl[(size_t)D_MODEL * D_MODEL];
__device__ __align__(16) __nv_bfloat16 g_woh[(size_t)D_MODEL * D_MODEL];
__device__ __align__(16) __nv_bfloat16 g_wol[(size_t)D_MODEL * D_MODEL];
__device__ __align__(16) __nv_bfloat16 g_w1h[(size_t)D_MODEL * D_FF];
__device__ __align__(16) __nv_bfloat16 g_w1l[(size_t)D_MODEL * D_FF];
__device__ __align__(16) __nv_bfloat16 g_w2h[(size_t)D_FF * D_MODEL];
__device__ __align__(16) __nv_bfloat16 g_w2l[(size_t)D_FF * D_MODEL];

// ---------------- helpers ----------------
__device__ __forceinline__ uint32_t smem_u32(const void* p) {
    uint32_t a;
    asm("{ .reg .u64 t; cvta.to.shared.u64 t, %1; cvt.u32.u64 %0, t; }" : "=r"(a) : "l"(p));
    return a;
}
__device__ __forceinline__ void cp16(uint32_t dst, const void* src) {
    asm volatile("cp.async.cg.shared.global [%0], [%1], 16;" :: "r"(dst), "l"(src));
}
__device__ __forceinline__ void cp_commit() {
    asm volatile("cp.async.commit_group;" ::: "memory");
}
template<int N>
__device__ __forceinline__ void cp_wait() {
    asm volatile("cp.async.wait_group %0;" :: "n"(N) : "memory");
}
__device__ __forceinline__ void ldsm_x4(uint32_t* r, uint32_t a) {
    asm volatile("ldmatrix.sync.aligned.m8n8.x4.shared.b16 {%0,%1,%2,%3}, [%4];"
                 : "=r"(r[0]), "=r"(r[1]), "=r"(r[2]), "=r"(r[3]) : "r"(a));
}
__device__ __forceinline__ void ldsm_x4t(uint32_t* r, uint32_t a) {
    asm volatile("ldmatrix.sync.aligned.m8n8.x4.trans.shared.b16 {%0,%1,%2,%3}, [%4];"
                 : "=r"(r[0]), "=r"(r[1]), "=r"(r[2]), "=r"(r[3]) : "r"(a));
}
__device__ __forceinline__ void mma16816(float* d, const uint32_t* a, uint32_t b0, uint32_t b1) {
    asm volatile("mma.sync.aligned.m16n8k16.row.col.f32.bf16.bf16.f32 "
                 "{%0,%1,%2,%3}, {%4,%5,%6,%7}, {%8,%9}, {%0,%1,%2,%3};"
                 : "+f"(d[0]), "+f"(d[1]), "+f"(d[2]), "+f"(d[3])
                 : "r"(a[0]), "r"(a[1]), "r"(a[2]), "r"(a[3]), "r"(b0), "r"(b1));
}
__device__ __forceinline__ void split2(float x, float y,
                                       __nv_bfloat162* h, __nv_bfloat162* l) {
    __nv_bfloat16 hx = __float2bfloat16_rn(x);
    __nv_bfloat16 hy = __float2bfloat16_rn(y);
    h->x = hx; h->y = hy;
    l->x = __float2bfloat16_rn(x - __bfloat162float(hx));
    l->y = __float2bfloat16_rn(y - __bfloat162float(hy));
}

// ---------------- fp32 -> bf16 hi/lo converter ----------------
__global__ void __launch_bounds__(256) conv_kernel(
    const float* __restrict__ W, __nv_bfloat16* __restrict__ Wh,
    __nv_bfloat16* __restrict__ Wl, int n4)
{
    int i = blockIdx.x * 256 + threadIdx.x;
    if (i >= n4) return;
    float4 v = ((const float4*)W)[i];
    __nv_bfloat162 h0, l0, h1, l1;
    split2(v.x, v.y, &h0, &l0);
    split2(v.z, v.w, &h1, &l1);
    ((__nv_bfloat162*)Wh)[2 * i]     = h0;
    ((__nv_bfloat162*)Wh)[2 * i + 1] = h1;
    ((__nv_bfloat162*)Wl)[2 * i]     = l0;
    ((__nv_bfloat162*)Wl)[2 * i + 1] = l1;
}

// ---------------- LayerNorm (+res), optional fp32 and bf16 hi/lo out -------
__global__ void __launch_bounds__(256) ln_kernel(
    const float* __restrict__ in, const float* __restrict__ res,
    const float* __restrict__ gam, const float* __restrict__ bet,
    float* __restrict__ outf, __nv_bfloat16* __restrict__ outh,
    __nv_bfloat16* __restrict__ outl)
{
    const int row = blockIdx.x, tid = threadIdx.x;
    const size_t base = (size_t)row * D_MODEL;
    float4 v = *(const float4*)(in + base + tid * 4);
    if (res) {
        float4 r = *(const float4*)(res + base + tid * 4);
        v.x += r.x; v.y += r.y; v.z += r.z; v.w += r.w;
    }
    float s  = v.x + v.y + v.z + v.w;
    float ss = v.x * v.x + v.y * v.y + v.z * v.z + v.w * v.w;
    #pragma unroll
    for (int o = 16; o > 0; o >>= 1) {
        s  += __shfl_down_sync(0xffffffffu, s,  o);
        ss += __shfl_down_sync(0xffffffffu, ss, o);
    }
    __shared__ float sh_s[8], sh_ss[8];
    const int w = tid >> 5, l = tid & 31;
    if (l == 0) { sh_s[w] = s; sh_ss[w] = ss; }
    __syncthreads();
    if (tid == 0) {
        float ts = 0.f, tss = 0.f;
        #pragma unroll
        for (int i = 0; i < 8; i++) { ts += sh_s[i]; tss += sh_ss[i]; }
        sh_s[0] = ts; sh_ss[0] = tss;
    }
    __syncthreads();
    const float mu  = sh_s[0] * (1.0f / D_MODEL);
    const float var = sh_ss[0] * (1.0f / D_MODEL) - mu * mu;
    const float inv = rsqrtf(var + 1e-6f);
    float4 g4 = *(const float4*)(gam + tid * 4);
    float4 b4 = *(const float4*)(bet + tid * 4);
    float4 o4;
    o4.x = (v.x - mu) * inv * g4.x + b4.x;
    o4.y = (v.y - mu) * inv * g4.y + b4.y;
    o4.z = (v.z - mu) * inv * g4.z + b4.z;
    o4.w = (v.w - mu) * inv * g4.w + b4.w;
    if (outf) *(float4*)(outf + base + tid * 4) = o4;
    if (outh) {
        __nv_bfloat162 h0, l0, h1, l1;
        split2(o4.x, o4.y, &h0, &l0);
        split2(o4.z, o4.w, &h1, &l1);
        *(__nv_bfloat162*)(outh + base + tid * 4)     = h0;
        *(__nv_bfloat162*)(outh + base + tid * 4 + 2) = h1;
        *(__nv_bfloat162*)(outl + base + tid * 4)     = l0;
        *(__nv_bfloat162*)(outl + base + tid * 4 + 2) = l1;
    }
}

// ---------------- per-token head-mixing attention (bf16 hi/lo out) --------
__global__ void __launch_bounds__(256) attn_kernel(
    const float* __restrict__ q, const float* __restrict__ k,
    const float* __restrict__ v, __nv_bfloat16* __restrict__ oh,
    __nv_bfloat16* __restrict__ ol)
{
    const int row = blockIdx.x, tid = threadIdx.x;
    __shared__ float sq[D_MODEL], sk[D_MODEL], sv[D_MODEL];
    __shared__ float sS[H_HEADS][H_HEADS + 1];
    const size_t base = (size_t)row * D_MODEL;
    ((float4*)sq)[tid] = *(const float4*)(q + base + tid * 4);
    ((float4*)sk)[tid] = *(const float4*)(k + base + tid * 4);
    ((float4*)sv)[tid] = *(const float4*)(v + base + tid * 4);
    __syncthreads();
    {
        const int h = tid >> 4, g = tid & 15;
        float s = 0.f;
        #pragma unroll
        for (int d = 0; d < DK; d++) s += sq[h * DK + d] * sk[g * DK + d];
        sS[h][g] = s * 0.125f;
    }
    __syncthreads();
    if (tid < H_HEADS) {
        float mx = -1e30f;
        #pragma unroll
        for (int g = 0; g < H_HEADS; g++) mx = fmaxf(mx, sS[tid][g]);
        float sum = 0.f;
        #pragma unroll
        for (int g = 0; g < H_HEADS; g++) {
            float e = expf(sS[tid][g] - mx);
            sS[tid][g] = e; sum += e;
        }
        const float invs = 1.0f / sum;
        #pragma unroll
        for (int g = 0; g < H_HEADS; g++) sS[tid][g] *= invs;
    }
    __syncthreads();
    const int b = row / T_SEQ, t = row % T_SEQ;
    const size_t ob = (size_t)b * T_SEQ * D_MODEL + (size_t)t * DK;
    #pragma unroll
    for (int i = 0; i < 4; i++) {
        const int idx = i * 256 + tid;
        const int h = idx >> 6, d = idx & 63;
        float acc = 0.f;
        #pragma unroll
        for (int g = 0; g < H_HEADS; g++) acc += sS[h][g] * sv[g * DK + d];
        const size_t off = ob + (size_t)h * T_SEQ * DK + d;
        __nv_bfloat16 hi = __float2bfloat16_rn(acc);
        oh[off] = hi;
        ol[off] = __float2bfloat16_rn(acc - __bfloat162float(hi));
    }
}

// ---------------- bf16 3-product HMMA GEMM, 128x256 tile, cp.async x3 ------
// C[M,Nn] = (Ah+Al)[M,K] @ (Bh+Bl)[K,Nn], fp32 acc.
// EPI: 0 fp32 out; 1 bias+GELU -> bf16 hi/lo out; 2 bias+res -> fp32 out
template<int EPI>
__global__ void __launch_bounds__(256, 1) hmma_gemm(
    const __nv_bfloat16* __restrict__ Ah, const __nv_bfloat16* __restrict__ Al,
    const __nv_bfloat16* __restrict__ Bh, const __nv_bfloat16* __restrict__ Bl,
    float* __restrict__ C, __nv_bfloat16* __restrict__ Ch, __nv_bfloat16* __restrict__ Cl,
    int K, int Nn, const float* __restrict__ bias, const float* __restrict__ res)
{
    extern __shared__ __align__(16) char sm[];
    const int tid = threadIdx.x, lane = tid & 31, wid = tid >> 5;
    const int bm = blockIdx.y, bn = blockIdx.x;
    const int wm = (wid >> 2) * 64, wn = (wid & 3) * 64;
    const uint32_t sb0 = smem_u32(sm);

    float acc[4][8][4];
    #pragma unroll
    for (int t = 0; t < 4; t++)
        #pragma unroll
        for (int j = 0; j < 8; j++)
            #pragma unroll
            for (int e = 0; e < 4; e++) acc[t][j][e] = 0.f;

    const int NK = K / 32;

    // loaders: A rows 128 x 64B (4 chunks/row); B rows 32 x 512B (32 chunks/row)
    auto load_stage = [&](int i, int s) {
        const uint32_t st = sb0 + s * STAGE_B;
        const int k0 = i * 32;
        #pragma unroll
        for (int j = 0; j < 2; j++) {
            const int ci = tid + j * 256;            // 0..511
            const int r = ci >> 2, c = ci & 3;
            const uint32_t dst = st + r * 64 + ((c ^ ((r >> 1) & 3)) << 4);
            const size_t src = (size_t)(bm * 128 + r) * K + k0 + c * 8;
            cp16(dst,        Ah + src);
            cp16(dst + 8192, Al + src);
        }
        #pragma unroll
        for (int j = 0; j < 4; j++) {
            const int ci = tid + j * 256;            // 0..1023
            const int r = ci >> 5, c = ci & 31;
            const uint32_t dst = st + 16384 + r * 512 + ((c ^ (r & 7)) << 4);
            const size_t src = (size_t)(k0 + r) * Nn + bn * 256 + c * 8;
            cp16(dst,         Bh + src);
            cp16(dst + 16384, Bl + src);
        }
    };

    load_stage(0, 0); cp_commit();
    if (NK > 1) { load_stage(1, 1); }
    cp_commit();

    for (int i = 0; i < NK; i++) {
        cp_wait<1>();
        __syncthreads();
        if (i + 2 < NK) load_stage(i + 2, (i + 2) % 3);
        cp_commit();

        const uint32_t st = sb0 + (i % 3) * STAGE_B;
        #pragma unroll
        for (int kk = 0; kk < 32; kk += 16) {
            uint32_t ah[4][4], al[4][4], bh[4][4], bl[4][4];
            const int acol = (kk >> 3) + ((lane >> 4) & 1);
            #pragma unroll
            for (int t = 0; t < 4; t++) {
                const int r = wm + t * 16 + (lane & 15);
                const uint32_t ad = st + r * 64 + ((acol ^ ((r >> 1) & 3)) << 4);
                ldsm_x4(ah[t], ad);
                ldsm_x4(al[t], ad + 8192);
            }
            const int rk = kk + (lane & 15);
            #pragma unroll
            for (int u = 0; u < 4; u++) {
                const int cB = (wn + u * 16 + ((lane & 16) ? 8 : 0)) >> 3;
                const uint32_t bd = st + 16384 + rk * 512 + ((cB ^ (rk & 7)) << 4);
                ldsm_x4t(bh[u], bd);
                ldsm_x4t(bl[u], bd + 16384);
            }
            // 3 passes so dependent accumulates are far apart
            #pragma unroll
            for (int t = 0; t < 4; t++)
                #pragma unroll
                for (int j = 0; j < 8; j++)
                    mma16816(acc[t][j], ah[t], bh[j >> 1][(j & 1) * 2], bh[j >> 1][(j & 1) * 2 + 1]);
            #pragma unroll
            for (int t = 0; t < 4; t++)
                #pragma unroll
                for (int j = 0; j < 8; j++)
                    mma16816(acc[t][j], ah[t], bl[j >> 1][(j & 1) * 2], bl[j >> 1][(j & 1) * 2 + 1]);
            #pragma unroll
            for (int t = 0; t < 4; t++)
                #pragma unroll
                for (int j = 0; j < 8; j++)
                    mma16816(acc[t][j], al[t], bh[j >> 1][(j & 1) * 2], bh[j >> 1][(j & 1) * 2 + 1]);
        }
        __syncthreads();
    }

    // epilogue
    const int l4 = lane >> 2, l2 = (lane & 3) * 2;
    #pragma unroll
    for (int t = 0; t < 4; t++)
        #pragma unroll
        for (int j = 0; j < 8; j++) {
            const int r0 = bm * 128 + wm + t * 16 + l4;
            const int c0 = bn * 256 + wn + j * 8 + l2;
            #pragma unroll
            for (int half = 0; half < 2; half++) {
                const int r = r0 + half * 8;
                float v0 = acc[t][j][half * 2];
                float v1 = acc[t][j][half * 2 + 1];
                if (EPI == 1) {
                    v0 += bias[c0];     v1 += bias[c0 + 1];
                    v0 = 0.5f * v0 * (1.0f + erff(v0 * 0.70710678118654752f));
                    v1 = 0.5f * v1 * (1.0f + erff(v1 * 0.70710678118654752f));
                    __nv_bfloat162 h2, l2b;
                    split2(v0, v1, &h2, &l2b);
                    *(__nv_bfloat162*)(Ch + (size_t)r * Nn + c0) = h2;
                    *(__nv_bfloat162*)(Cl + (size_t)r * Nn + c0) = l2b;
                } else {
                    if (EPI == 2) {
                        float2 rr = *(const float2*)(res + (size_t)r * Nn + c0);
                        v0 += bias[c0] + rr.x;
                        v1 += bias[c0 + 1] + rr.y;
                    }
                    *(float2*)(C + (size_t)r * Nn + c0) = make_float2(v0, v1);
                }
            }
        }
}

// ---------------- launch ----------------
extern "C" void kernel_launch(void* const* d_in, const int* in_sizes, int n_in,
                              void* d_out, int out_size)
{
    const float* x     = (const float*)d_in[0];
    const float* wq    = (const float*)d_in[1];
    const float* wk    = (const float*)d_in[2];
    const float* wv    = (const float*)d_in[3];
    const float* wo    = (const float*)d_in[4];
    const float* ln1g  = (const float*)d_in[5];
    const float* ln1b  = (const float*)d_in[6];
    const float* w1    = (const float*)d_in[7];
    const float* b1    = (const float*)d_in[8];
    const float* w2    = (const float*)d_in[9];
    const float* b2    = (const float*)d_in[10];
    const float* ln2g  = (const float*)d_in[11];
    const float* ln2b  = (const float*)d_in[12];
    float* out = (float*)d_out;

    float *q, *k, *v, *o2, *q2, *y;
    __nv_bfloat16 *x1h, *x1l, *osh, *osl, *q2h, *q2l, *hh, *hl;
    __nv_bfloat16 *wqh, *wql, *wkh, *wkl, *wvh, *wvl, *woh, *wol, *w1h, *w1l, *w2h, *w2l;
    cudaGetSymbolAddress((void**)&q,  g_q);
    cudaGetSymbolAddress((void**)&k,  g_k);
    cudaGetSymbolAddress((void**)&v,  g_v);
    cudaGetSymbolAddress((void**)&o2, g_o2);
    cudaGetSymbolAddress((void**)&q2, g_q2);
    cudaGetSymbolAddress((void**)&y,  g_y);
    cudaGetSymbolAddress((void**)&x1h, g_x1h);
    cudaGetSymbolAddress((void**)&x1l, g_x1l);
    cudaGetSymbolAddress((void**)&osh, g_osh);
    cudaGetSymbolAddress((void**)&osl, g_osl);
    cudaGetSymbolAddress((void**)&q2h, g_q2h);
    cudaGetSymbolAddress((void**)&q2l, g_q2l);
    cudaGetSymbolAddress((void**)&hh,  g_hh);
    cudaGetSymbolAddress((void**)&hl,  g_hl);
    cudaGetSymbolAddress((void**)&wqh, g_wqh);
    cudaGetSymbolAddress((void**)&wql, g_wql);
    cudaGetSymbolAddress((void**)&wkh, g_wkh);
    cudaGetSymbolAddress((void**)&wkl, g_wkl);
    cudaGetSymbolAddress((void**)&wvh, g_wvh);
    cudaGetSymbolAddress((void**)&wvl, g_wvl);
    cudaGetSymbolAddress((void**)&woh, g_woh);
    cudaGetSymbolAddress((void**)&wol, g_wol);
    cudaGetSymbolAddress((void**)&w1h, g_w1h);
    cudaGetSymbolAddress((void**)&w1l, g_w1l);
    cudaGetSymbolAddress((void**)&w2h, g_w2h);
    cudaGetSymbolAddress((void**)&w2l, g_w2l);

    cudaFuncSetAttribute(hmma_gemm<0>, cudaFuncAttributeMaxDynamicSharedMemorySize, GEMM_SMEM);
    cudaFuncSetAttribute(hmma_gemm<1>, cudaFuncAttributeMaxDynamicSharedMemorySize, GEMM_SMEM);
    cudaFuncSetAttribute(hmma_gemm<2>, cudaFuncAttributeMaxDynamicSharedMemorySize, GEMM_SMEM);

    const int nDD4 = D_MODEL * D_MODEL / 4;
    const int nDF4 = D_MODEL * D_FF / 4;
    conv_kernel<<<nDD4 / 256, 256>>>(wq, wqh, wql, nDD4);
    conv_kernel<<<nDD4 / 256, 256>>>(wk, wkh, wkl, nDD4);
    conv_kernel<<<nDD4 / 256, 256>>>(wv, wvh, wvl, nDD4);
    conv_kernel<<<nDD4 / 256, 256>>>(wo, woh, wol, nDD4);
    conv_kernel<<<nDF4 / 256, 256>>>(w1, w1h, w1l, nDF4);
    conv_kernel<<<nDF4 / 256, 256>>>(w2, w2h, w2l, nDF4);

    const dim3 gD(D_MODEL / 256, N_TOK / 128);   // (4, 128)
    const dim3 gF(D_FF    / 256, N_TOK / 128);   // (16, 128)

    ln_kernel<<<N_TOK, 256>>>(x, nullptr, ln1g, ln1b, nullptr, x1h, x1l);
    hmma_gemm<0><<<gD, 256, GEMM_SMEM>>>(x1h, x1l, wqh, wql, q, nullptr, nullptr,
                                         D_MODEL, D_MODEL, nullptr, nullptr);
    hmma_gemm<0><<<gD, 256, GEMM_SMEM>>>(x1h, x1l, wkh, wkl, k, nullptr, nullptr,
                                         D_MODEL, D_MODEL, nullptr, nullptr);
    hmma_gemm<0><<<gD, 256, GEMM_SMEM>>>(x1h, x1l, wvh, wvl, v, nullptr, nullptr,
                                         D_MODEL, D_MODEL, nullptr, nullptr);
    attn_kernel<<<N_TOK, 256>>>(q, k, v, osh, osl);
    hmma_gemm<0><<<gD, 256, GEMM_SMEM>>>(osh, osl, woh, wol, o2, nullptr, nullptr,
                                         D_MODEL, D_MODEL, nullptr, nullptr);
    ln_kernel<<<N_TOK, 256>>>(o2, x, ln1g, ln1b, q2, q2h, q2l);
    hmma_gemm<1><<<gF, 256, GEMM_SMEM>>>(q2h, q2l, w1h, w1l, nullptr, hh, hl,
                                         D_MODEL, D_FF, b1, nullptr);
    hmma_gemm<2><<<gD, 256, GEMM_SMEM>>>(hh, hl, w2h, w2l, y, nullptr, nullptr,
                                         D_FF, D_MODEL, b2, q2);
    ln_kernel<<<N_TOK, 256>>>(y, nullptr, ln2g, ln2b, out, nullptr, nullptr);
}

// round 10
// speedup vs baseline: 2.6062x; 1.0268x over previous
#include <cuda_runtime.h>
#include <cuda_bf16.h>
#include <math.h>
#include <stdint.h>

#define D_MODEL 1024
#define D_FF    4096
#define T_SEQ   4096
#define N_TOK   16384
#define H_HEADS 16
#define DK      64

#define STAGE_B   49152              // Ah 8K | Al 8K | Bh 16K | Bl 16K
#define GEMM_SMEM (3 * STAGE_B)      // 144 KB, 3-stage pipeline

// ---------------- device scratch ----------------
__device__ float g_q [(size_t)N_TOK * D_MODEL];
__device__ float g_k [(size_t)N_TOK * D_MODEL];
__device__ float g_v [(size_t)N_TOK * D_MODEL];
__device__ float g_o2[(size_t)N_TOK * D_MODEL];
__device__ float g_q2[(size_t)N_TOK * D_MODEL];
__device__ float g_y [(size_t)N_TOK * D_MODEL];

__device__ __align__(16) __nv_bfloat16 g_x1h[(size_t)N_TOK * D_MODEL];
__device__ __align__(16) __nv_bfloat16 g_x1l[(size_t)N_TOK * D_MODEL];
__device__ __align__(16) __nv_bfloat16 g_osh[(size_t)N_TOK * D_MODEL];
__device__ __align__(16) __nv_bfloat16 g_osl[(size_t)N_TOK * D_MODEL];
__device__ __align__(16) __nv_bfloat16 g_q2h[(size_t)N_TOK * D_MODEL];
__device__ __align__(16) __nv_bfloat16 g_q2l[(size_t)N_TOK * D_MODEL];
__device__ __align__(16) __nv_bfloat16 g_hh [(size_t)N_TOK * D_FF];
__device__ __align__(16) __nv_bfloat16 g_hl [(size_t)N_TOK * D_FF];
__device__ __align__(16) __nv_bfloat16 g_wqh[(size_t)D_MODEL * D_MODEL];
__device__ __align__(16) __nv_bfloat16 g_wql[(size_t)D_MODEL * D_MODEL];
__device__ __align__(16) __nv_bfloat16 g_wkh[(size_t)D_MODEL * D_MODEL];
__device__ __align__(16) __nv_bfloat16 g_wkl[(size_t)D_MODEL * D_MODEL];
__device__ __align__(16) __nv_bfloat16 g_wvh[(size_t)D_MODEL * D_MODEL];
__device__ __align__(16) __nv_bfloat16 g_wvl[(size_t)D_MODEL * D_MODEL];
__device__ __align__(16) __nv_bfloat16 g_woh[(size_t)D_MODEL * D_MODEL];
__device__ __align__(16) __nv_bfloat16 g_wol[(size_t)D_MODEL * D_MODEL];
__device__ __align__(16) __nv_bfloat16 g_w1h[(size_t)D_MODEL * D_FF];
__device__ __align__(16) __nv_bfloat16 g_w1l[(size_t)D_MODEL * D_FF];
__device__ __align__(16) __nv_bfloat16 g_w2h[(size_t)D_FF * D_MODEL];
__device__ __align__(16) __nv_bfloat16 g_w2l[(size_t)D_FF * D_MODEL];

// ---------------- helpers ----------------
__device__ __forceinline__ uint32_t smem_u32(const void* p) {
    uint32_t a;
    asm("{ .reg .u64 t; cvta.to.shared.u64 t, %1; cvt.u32.u64 %0, t; }" : "=r"(a) : "l"(p));
    return a;
}
__device__ __forceinline__ void cp16(uint32_t dst, const void* src) {
    asm volatile("cp.async.cg.shared.global [%0], [%1], 16;" :: "r"(dst), "l"(src));
}
__device__ __forceinline__ void cp_commit() {
    asm volatile("cp.async.commit_group;" ::: "memory");
}
template<int N>
__device__ __forceinline__ void cp_wait() {
    asm volatile("cp.async.wait_group %0;" :: "n"(N) : "memory");
}
__device__ __forceinline__ void ldsm_x4(uint32_t* r, uint32_t a) {
    asm volatile("ldmatrix.sync.aligned.m8n8.x4.shared.b16 {%0,%1,%2,%3}, [%4];"
                 : "=r"(r[0]), "=r"(r[1]), "=r"(r[2]), "=r"(r[3]) : "r"(a));
}
__device__ __forceinline__ void ldsm_x4t(uint32_t* r, uint32_t a) {
    asm volatile("ldmatrix.sync.aligned.m8n8.x4.trans.shared.b16 {%0,%1,%2,%3}, [%4];"
                 : "=r"(r[0]), "=r"(r[1]), "=r"(r[2]), "=r"(r[3]) : "r"(a));
}
__device__ __forceinline__ void mma16816(float* d, const uint32_t* a, uint32_t b0, uint32_t b1) {
    asm volatile("mma.sync.aligned.m16n8k16.row.col.f32.bf16.bf16.f32 "
                 "{%0,%1,%2,%3}, {%4,%5,%6,%7}, {%8,%9}, {%0,%1,%2,%3};"
                 : "+f"(d[0]), "+f"(d[1]), "+f"(d[2]), "+f"(d[3])
                 : "r"(a[0]), "r"(a[1]), "r"(a[2]), "r"(a[3]), "r"(b0), "r"(b1));
}
__device__ __forceinline__ void split2(float x, float y,
                                       __nv_bfloat162* h, __nv_bfloat162* l) {
    __nv_bfloat16 hx = __float2bfloat16_rn(x);
    __nv_bfloat16 hy = __float2bfloat16_rn(y);
    h->x = hx; h->y = hy;
    l->x = __float2bfloat16_rn(x - __bfloat162float(hx));
    l->y = __float2bfloat16_rn(y - __bfloat162float(hy));
}

// ---------------- fp32 -> bf16 hi/lo converter ----------------
__global__ void __launch_bounds__(256) conv_kernel(
    const float* __restrict__ W, __nv_bfloat16* __restrict__ Wh,
    __nv_bfloat16* __restrict__ Wl, int n4)
{
    int i = blockIdx.x * 256 + threadIdx.x;
    if (i >= n4) return;
    float4 v = ((const float4*)W)[i];
    __nv_bfloat162 h0, l0, h1, l1;
    split2(v.x, v.y, &h0, &l0);
    split2(v.z, v.w, &h1, &l1);
    ((__nv_bfloat162*)Wh)[2 * i]     = h0;
    ((__nv_bfloat162*)Wh)[2 * i + 1] = h1;
    ((__nv_bfloat162*)Wl)[2 * i]     = l0;
    ((__nv_bfloat162*)Wl)[2 * i + 1] = l1;
}

// ---------------- LayerNorm (+res), optional fp32 and bf16 hi/lo out -------
__global__ void __launch_bounds__(256) ln_kernel(
    const float* __restrict__ in, const float* __restrict__ res,
    const float* __restrict__ gam, const float* __restrict__ bet,
    float* __restrict__ outf, __nv_bfloat16* __restrict__ outh,
    __nv_bfloat16* __restrict__ outl)
{
    const int row = blockIdx.x, tid = threadIdx.x;
    const size_t base = (size_t)row * D_MODEL;
    float4 v = *(const float4*)(in + base + tid * 4);
    if (res) {
        float4 r = *(const float4*)(res + base + tid * 4);
        v.x += r.x; v.y += r.y; v.z += r.z; v.w += r.w;
    }
    float s  = v.x + v.y + v.z + v.w;
    float ss = v.x * v.x + v.y * v.y + v.z * v.z + v.w * v.w;
    #pragma unroll
    for (int o = 16; o > 0; o >>= 1) {
        s  += __shfl_down_sync(0xffffffffu, s,  o);
        ss += __shfl_down_sync(0xffffffffu, ss, o);
    }
    __shared__ float sh_s[8], sh_ss[8];
    const int w = tid >> 5, l = tid & 31;
    if (l == 0) { sh_s[w] = s; sh_ss[w] = ss; }
    __syncthreads();
    if (tid == 0) {
        float ts = 0.f, tss = 0.f;
        #pragma unroll
        for (int i = 0; i < 8; i++) { ts += sh_s[i]; tss += sh_ss[i]; }
        sh_s[0] = ts; sh_ss[0] = tss;
    }
    __syncthreads();
    const float mu  = sh_s[0] * (1.0f / D_MODEL);
    const float var = sh_ss[0] * (1.0f / D_MODEL) - mu * mu;
    const float inv = rsqrtf(var + 1e-6f);
    float4 g4 = *(const float4*)(gam + tid * 4);
    float4 b4 = *(const float4*)(bet + tid * 4);
    float4 o4;
    o4.x = (v.x - mu) * inv * g4.x + b4.x;
    o4.y = (v.y - mu) * inv * g4.y + b4.y;
    o4.z = (v.z - mu) * inv * g4.z + b4.z;
    o4.w = (v.w - mu) * inv * g4.w + b4.w;
    if (outf) *(float4*)(outf + base + tid * 4) = o4;
    if (outh) {
        __nv_bfloat162 h0, l0, h1, l1;
        split2(o4.x, o4.y, &h0, &l0);
        split2(o4.z, o4.w, &h1, &l1);
        *(__nv_bfloat162*)(outh + base + tid * 4)     = h0;
        *(__nv_bfloat162*)(outh + base + tid * 4 + 2) = h1;
        *(__nv_bfloat162*)(outl + base + tid * 4)     = l0;
        *(__nv_bfloat162*)(outl + base + tid * 4 + 2) = l1;
    }
}

// ---------------- per-token head-mixing attention (bf16 hi/lo out) --------
__global__ void __launch_bounds__(256) attn_kernel(
    const float* __restrict__ q, const float* __restrict__ k,
    const float* __restrict__ v, __nv_bfloat16* __restrict__ oh,
    __nv_bfloat16* __restrict__ ol)
{
    const int row = blockIdx.x, tid = threadIdx.x;
    __shared__ float sq[D_MODEL], sk[D_MODEL], sv[D_MODEL];
    __shared__ float sS[H_HEADS][H_HEADS + 1];
    const size_t base = (size_t)row * D_MODEL;
    ((float4*)sq)[tid] = *(const float4*)(q + base + tid * 4);
    ((float4*)sk)[tid] = *(const float4*)(k + base + tid * 4);
    ((float4*)sv)[tid] = *(const float4*)(v + base + tid * 4);
    __syncthreads();
    {
        const int h = tid >> 4, g = tid & 15;
        float s = 0.f;
        #pragma unroll
        for (int d = 0; d < DK; d++) s += sq[h * DK + d] * sk[g * DK + d];
        sS[h][g] = s * 0.125f;
    }
    __syncthreads();
    if (tid < H_HEADS) {
        float mx = -1e30f;
        #pragma unroll
        for (int g = 0; g < H_HEADS; g++) mx = fmaxf(mx, sS[tid][g]);
        float sum = 0.f;
        #pragma unroll
        for (int g = 0; g < H_HEADS; g++) {
            float e = expf(sS[tid][g] - mx);
            sS[tid][g] = e; sum += e;
        }
        const float invs = 1.0f / sum;
        #pragma unroll
        for (int g = 0; g < H_HEADS; g++) sS[tid][g] *= invs;
    }
    __syncthreads();
    const int b = row / T_SEQ, t = row % T_SEQ;
    const size_t ob = (size_t)b * T_SEQ * D_MODEL + (size_t)t * DK;
    #pragma unroll
    for (int i = 0; i < 4; i++) {
        const int idx = i * 256 + tid;
        const int h = idx >> 6, d = idx & 63;
        float acc = 0.f;
        #pragma unroll
        for (int g = 0; g < H_HEADS; g++) acc += sS[h][g] * sv[g * DK + d];
        const size_t off = ob + (size_t)h * T_SEQ * DK + d;
        __nv_bfloat16 hi = __float2bfloat16_rn(acc);
        oh[off] = hi;
        ol[off] = __float2bfloat16_rn(acc - __bfloat162float(hi));
    }
}

// ---------------- bf16 3-product HMMA GEMM, 128x256 tile, 512 thr ---------
// 16 warps: grid 2 (M) x 8 (N), warp tile 64x32. 3-stage cp.async pipeline.
// EPI: 0 fp32 out; 1 bias+GELU -> bf16 hi/lo out; 2 bias+res -> fp32 out
template<int EPI>
__global__ void __launch_bounds__(512, 1) hmma_gemm(
    const __nv_bfloat16* __restrict__ Ah, const __nv_bfloat16* __restrict__ Al,
    const __nv_bfloat16* __restrict__ Bh, const __nv_bfloat16* __restrict__ Bl,
    float* __restrict__ C, __nv_bfloat16* __restrict__ Ch, __nv_bfloat16* __restrict__ Cl,
    int K, int Nn, const float* __restrict__ bias, const float* __restrict__ res)
{
    extern __shared__ __align__(16) char sm[];
    const int tid = threadIdx.x, lane = tid & 31, wid = tid >> 5;
    const int bm = blockIdx.y, bn = blockIdx.x;
    const int wm = (wid >> 3) * 64;        // 0 or 64
    const int wn = (wid & 7) * 32;         // 0..224
    const uint32_t sb0 = smem_u32(sm);

    float acc[4][4][4];
    #pragma unroll
    for (int t = 0; t < 4; t++)
        #pragma unroll
        for (int j = 0; j < 4; j++)
            #pragma unroll
            for (int e = 0; e < 4; e++) acc[t][j][e] = 0.f;

    const int NK = K / 32;

    auto load_stage = [&](int i, int s) {
        const uint32_t st = sb0 + s * STAGE_B;
        const int k0 = i * 32;
        {   // A: 128 rows x 64B, 512 chunks, 1/thread per h|l
            const int r = tid >> 2, c = tid & 3;
            const uint32_t dst = st + r * 64 + ((c ^ ((r >> 1) & 3)) << 4);
            const size_t src = (size_t)(bm * 128 + r) * K + k0 + c * 8;
            cp16(dst,        Ah + src);
            cp16(dst + 8192, Al + src);
        }
        #pragma unroll
        for (int j = 0; j < 2; j++) {   // B: 32 rows x 512B, 1024 chunks
            const int ci = tid + j * 512;
            const int r = ci >> 5, c = ci & 31;
            const uint32_t dst = st + 16384 + r * 512 + ((c ^ (r & 7)) << 4);
            const size_t src = (size_t)(k0 + r) * Nn + bn * 256 + c * 8;
            cp16(dst,         Bh + src);
            cp16(dst + 16384, Bl + src);
        }
    };

    load_stage(0, 0); cp_commit();
    if (NK > 1) load_stage(1, 1);
    cp_commit();

    for (int i = 0; i < NK; i++) {
        cp_wait<1>();
        __syncthreads();
        if (i + 2 < NK) load_stage(i + 2, (i + 2) % 3);
        cp_commit();

        const uint32_t st = sb0 + (i % 3) * STAGE_B;
        #pragma unroll
        for (int kk = 0; kk < 32; kk += 16) {
            uint32_t ah[4][4], al[4][4], bh[2][4], bl[2][4];
            const int acol = (kk >> 3) + ((lane >> 4) & 1);
            #pragma unroll
            for (int t = 0; t < 4; t++) {
                const int r = wm + t * 16 + (lane & 15);
                const uint32_t ad = st + r * 64 + ((acol ^ ((r >> 1) & 3)) << 4);
                ldsm_x4(ah[t], ad);
                ldsm_x4(al[t], ad + 8192);
            }
            const int rk = kk + (lane & 15);
            #pragma unroll
            for (int u = 0; u < 2; u++) {
                const int cB = (wn + u * 16 + ((lane & 16) ? 8 : 0)) >> 3;
                const uint32_t bd = st + 16384 + rk * 512 + ((cB ^ (rk & 7)) << 4);
                ldsm_x4t(bh[u], bd);
                ldsm_x4t(bl[u], bd + 16384);
            }
            // pass 1: Ah*Bh
            #pragma unroll
            for (int t = 0; t < 4; t++)
                #pragma unroll
                for (int j = 0; j < 4; j++)
                    mma16816(acc[t][j], ah[t], bh[j >> 1][(j & 1) * 2], bh[j >> 1][(j & 1) * 2 + 1]);
            // pass 2: Ah*Bl
            #pragma unroll
            for (int t = 0; t < 4; t++)
                #pragma unroll
                for (int j = 0; j < 4; j++)
                    mma16816(acc[t][j], ah[t], bl[j >> 1][(j & 1) * 2], bl[j >> 1][(j & 1) * 2 + 1]);
            // pass 3: Al*Bh
            #pragma unroll
            for (int t = 0; t < 4; t++)
                #pragma unroll
                for (int j = 0; j < 4; j++)
                    mma16816(acc[t][j], al[t], bh[j >> 1][(j & 1) * 2], bh[j >> 1][(j & 1) * 2 + 1]);
        }
        // no trailing barrier needed: 3-stage ring + top-of-loop barrier
        // already orders the next overwrite after all reads.
    }

    // epilogue
    const int l4 = lane >> 2, l2 = (lane & 3) * 2;
    #pragma unroll
    for (int t = 0; t < 4; t++)
        #pragma unroll
        for (int j = 0; j < 4; j++) {
            const int r0 = bm * 128 + wm + t * 16 + l4;
            const int c0 = bn * 256 + wn + j * 8 + l2;
            #pragma unroll
            for (int half = 0; half < 2; half++) {
                const int r = r0 + half * 8;
                float v0 = acc[t][j][half * 2];
                float v1 = acc[t][j][half * 2 + 1];
                if (EPI == 1) {
                    v0 += bias[c0];     v1 += bias[c0 + 1];
                    v0 = 0.5f * v0 * (1.0f + erff(v0 * 0.70710678118654752f));
                    v1 = 0.5f * v1 * (1.0f + erff(v1 * 0.70710678118654752f));
                    __nv_bfloat162 h2, l2b;
                    split2(v0, v1, &h2, &l2b);
                    *(__nv_bfloat162*)(Ch + (size_t)r * Nn + c0) = h2;
                    *(__nv_bfloat162*)(Cl + (size_t)r * Nn + c0) = l2b;
                } else {
                    if (EPI == 2) {
                        float2 rr = *(const float2*)(res + (size_t)r * Nn + c0);
                        v0 += bias[c0] + rr.x;
                        v1 += bias[c0 + 1] + rr.y;
                    }
                    *(float2*)(C + (size_t)r * Nn + c0) = make_float2(v0, v1);
                }
            }
        }
}

// ---------------- launch ----------------
extern "C" void kernel_launch(void* const* d_in, const int* in_sizes, int n_in,
                              void* d_out, int out_size)
{
    const float* x     = (const float*)d_in[0];
    const float* wq    = (const float*)d_in[1];
    const float* wk    = (const float*)d_in[2];
    const float* wv    = (const float*)d_in[3];
    const float* wo    = (const float*)d_in[4];
    const float* ln1g  = (const float*)d_in[5];
    const float* ln1b  = (const float*)d_in[6];
    const float* w1    = (const float*)d_in[7];
    const float* b1    = (const float*)d_in[8];
    const float* w2    = (const float*)d_in[9];
    const float* b2    = (const float*)d_in[10];
    const float* ln2g  = (const float*)d_in[11];
    const float* ln2b  = (const float*)d_in[12];
    float* out = (float*)d_out;

    float *q, *k, *v, *o2, *q2, *y;
    __nv_bfloat16 *x1h, *x1l, *osh, *osl, *q2h, *q2l, *hh, *hl;
    __nv_bfloat16 *wqh, *wql, *wkh, *wkl, *wvh, *wvl, *woh, *wol, *w1h, *w1l, *w2h, *w2l;
    cudaGetSymbolAddress((void**)&q,  g_q);
    cudaGetSymbolAddress((void**)&k,  g_k);
    cudaGetSymbolAddress((void**)&v,  g_v);
    cudaGetSymbolAddress((void**)&o2, g_o2);
    cudaGetSymbolAddress((void**)&q2, g_q2);
    cudaGetSymbolAddress((void**)&y,  g_y);
    cudaGetSymbolAddress((void**)&x1h, g_x1h);
    cudaGetSymbolAddress((void**)&x1l, g_x1l);
    cudaGetSymbolAddress((void**)&osh, g_osh);
    cudaGetSymbolAddress((void**)&osl, g_osl);
    cudaGetSymbolAddress((void**)&q2h, g_q2h);
    cudaGetSymbolAddress((void**)&q2l, g_q2l);
    cudaGetSymbolAddress((void**)&hh,  g_hh);
    cudaGetSymbolAddress((void**)&hl,  g_hl);
    cudaGetSymbolAddress((void**)&wqh, g_wqh);
    cudaGetSymbolAddress((void**)&wql, g_wql);
    cudaGetSymbolAddress((void**)&wkh, g_wkh);
    cudaGetSymbolAddress((void**)&wkl, g_wkl);
    cudaGetSymbolAddress((void**)&wvh, g_wvh);
    cudaGetSymbolAddress((void**)&wvl, g_wvl);
    cudaGetSymbolAddress((void**)&woh, g_woh);
    cudaGetSymbolAddress((void**)&wol, g_wol);
    cudaGetSymbolAddress((void**)&w1h, g_w1h);
    cudaGetSymbolAddress((void**)&w1l, g_w1l);
    cudaGetSymbolAddress((void**)&w2h, g_w2h);
    cudaGetSymbolAddress((void**)&w2l, g_w2l);

    cudaFuncSetAttribute(hmma_gemm<0>, cudaFuncAttributeMaxDynamicSharedMemorySize, GEMM_SMEM);
    cudaFuncSetAttribute(hmma_gemm<1>, cudaFuncAttributeMaxDynamicSharedMemorySize, GEMM_SMEM);
    cudaFuncSetAttribute(hmma_gemm<2>, cudaFuncAttributeMaxDynamicSharedMemorySize, GEMM_SMEM);

    const int nDD4 = D_MODEL * D_MODEL / 4;
    const int nDF4 = D_MODEL * D_FF / 4;
    conv_kernel<<<nDD4 / 256, 256>>>(wq, wqh, wql, nDD4);
    conv_kernel<<<nDD4 / 256, 256>>>(wk, wkh, wkl, nDD4);
    conv_kernel<<<nDD4 / 256, 256>>>(wv, wvh, wvl, nDD4);
    conv_kernel<<<nDD4 / 256, 256>>>(wo, woh, wol, nDD4);
    conv_kernel<<<nDF4 / 256, 256>>>(w1, w1h, w1l, nDF4);
    conv_kernel<<<nDF4 / 256, 256>>>(w2, w2h, w2l, nDF4);

    const dim3 gD(D_MODEL / 256, N_TOK / 128);   // (4, 128)
    const dim3 gF(D_FF    / 256, N_TOK / 128);   // (16, 128)

    ln_kernel<<<N_TOK, 256>>>(x, nullptr, ln1g, ln1b, nullptr, x1h, x1l);
    hmma_gemm<0><<<gD, 512, GEMM_SMEM>>>(x1h, x1l, wqh, wql, q, nullptr, nullptr,
                                         D_MODEL, D_MODEL, nullptr, nullptr);
    hmma_gemm<0><<<gD, 512, GEMM_SMEM>>>(x1h, x1l, wkh, wkl, k, nullptr, nullptr,
                                         D_MODEL, D_MODEL, nullptr, nullptr);
    hmma_gemm<0><<<gD, 512, GEMM_SMEM>>>(x1h, x1l, wvh, wvl, v, nullptr, nullptr,
                                         D_MODEL, D_MODEL, nullptr, nullptr);
    attn_kernel<<<N_TOK, 256>>>(q, k, v, osh, osl);
    hmma_gemm<0><<<gD, 512, GEMM_SMEM>>>(osh, osl, woh, wol, o2, nullptr, nullptr,
                                         D_MODEL, D_MODEL, nullptr, nullptr);
    ln_kernel<<<N_TOK, 256>>>(o2, x, ln1g, ln1b, q2, q2h, q2l);
    hmma_gemm<1><<<gF, 512, GEMM_SMEM>>>(q2h, q2l, w1h, w1l, nullptr, hh, hl,
                                         D_MODEL, D_FF, b1, nullptr);
    hmma_gemm<2><<<gD, 512, GEMM_SMEM>>>(hh, hl, w2h, w2l, y, nullptr, nullptr,
                                         D_FF, D_MODEL, b2, q2);
    ln_kernel<<<N_TOK, 256>>>(y, nullptr, ln2g, ln2b, out, nullptr, nullptr);
}

// round 11
// speedup vs baseline: 3.4354x; 1.3182x over previous
#include <cuda_runtime.h>
#include <cuda_fp16.h>
#include <math.h>
#include <stdint.h>

#define D_MODEL 1024
#define D_FF    4096
#define T_SEQ   4096
#define N_TOK   16384
#define H_HEADS 16
#define DK      64

#define STAGE_B   32768              // Ah 8K | Al 8K | Bh 16K
#define GEMM_SMEM (3 * STAGE_B)      // 96 KB, 3-stage pipeline

// ---------------- device scratch ----------------
__device__ float g_q [(size_t)N_TOK * D_MODEL];
__device__ float g_k [(size_t)N_TOK * D_MODEL];
__device__ float g_v [(size_t)N_TOK * D_MODEL];
__device__ float g_o2[(size_t)N_TOK * D_MODEL];
__device__ float g_q2[(size_t)N_TOK * D_MODEL];
__device__ float g_y [(size_t)N_TOK * D_MODEL];

__device__ __align__(16) __half g_x1h[(size_t)N_TOK * D_MODEL];
__device__ __align__(16) __half g_x1l[(size_t)N_TOK * D_MODEL];
__device__ __align__(16) __half g_osh[(size_t)N_TOK * D_MODEL];
__device__ __align__(16) __half g_osl[(size_t)N_TOK * D_MODEL];
__device__ __align__(16) __half g_q2h[(size_t)N_TOK * D_MODEL];
__device__ __align__(16) __half g_q2l[(size_t)N_TOK * D_MODEL];
__device__ __align__(16) __half g_hh [(size_t)N_TOK * D_FF];
__device__ __align__(16) __half g_hl [(size_t)N_TOK * D_FF];
__device__ __align__(16) __half g_wqh[(size_t)D_MODEL * D_MODEL];
__device__ __align__(16) __half g_wkh[(size_t)D_MODEL * D_MODEL];
__device__ __align__(16) __half g_wvh[(size_t)D_MODEL * D_MODEL];
__device__ __align__(16) __half g_woh[(size_t)D_MODEL * D_MODEL];
__device__ __align__(16) __half g_w1h[(size_t)D_MODEL * D_FF];
__device__ __align__(16) __half g_w2h[(size_t)D_FF * D_MODEL];

// ---------------- helpers ----------------
__device__ __forceinline__ uint32_t smem_u32(const void* p) {
    uint32_t a;
    asm("{ .reg .u64 t; cvta.to.shared.u64 t, %1; cvt.u32.u64 %0, t; }" : "=r"(a) : "l"(p));
    return a;
}
__device__ __forceinline__ void cp16(uint32_t dst, const void* src) {
    asm volatile("cp.async.cg.shared.global [%0], [%1], 16;" :: "r"(dst), "l"(src));
}
__device__ __forceinline__ void cp_commit() {
    asm volatile("cp.async.commit_group;" ::: "memory");
}
template<int N>
__device__ __forceinline__ void cp_wait() {
    asm volatile("cp.async.wait_group %0;" :: "n"(N) : "memory");
}
__device__ __forceinline__ void ldsm_x4(uint32_t* r, uint32_t a) {
    asm volatile("ldmatrix.sync.aligned.m8n8.x4.shared.b16 {%0,%1,%2,%3}, [%4];"
                 : "=r"(r[0]), "=r"(r[1]), "=r"(r[2]), "=r"(r[3]) : "r"(a));
}
__device__ __forceinline__ void ldsm_x4t(uint32_t* r, uint32_t a) {
    asm volatile("ldmatrix.sync.aligned.m8n8.x4.trans.shared.b16 {%0,%1,%2,%3}, [%4];"
                 : "=r"(r[0]), "=r"(r[1]), "=r"(r[2]), "=r"(r[3]) : "r"(a));
}
__device__ __forceinline__ void mma16816(float* d, const uint32_t* a, uint32_t b0, uint32_t b1) {
    asm volatile("mma.sync.aligned.m16n8k16.row.col.f32.f16.f16.f32 "
                 "{%0,%1,%2,%3}, {%4,%5,%6,%7}, {%8,%9}, {%0,%1,%2,%3};"
                 : "+f"(d[0]), "+f"(d[1]), "+f"(d[2]), "+f"(d[3])
                 : "r"(a[0]), "r"(a[1]), "r"(a[2]), "r"(a[3]), "r"(b0), "r"(b1));
}
__device__ __forceinline__ void split2h(float x, float y, __half2* h, __half2* l) {
    __half hx = __float2half_rn(x);
    __half hy = __float2half_rn(y);
    *h = __halves2half2(hx, hy);
    *l = __halves2half2(__float2half_rn(x - __half2float(hx)),
                        __float2half_rn(y - __half2float(hy)));
}

// ---------------- fp32 -> fp16 (weights: hi only) ----------------
__global__ void __launch_bounds__(256) convw_kernel(
    const float* __restrict__ W, __half* __restrict__ Wh, int n4)
{
    int i = blockIdx.x * 256 + threadIdx.x;
    if (i >= n4) return;
    float4 v = ((const float4*)W)[i];
    __half2 h0 = __halves2half2(__float2half_rn(v.x), __float2half_rn(v.y));
    __half2 h1 = __halves2half2(__float2half_rn(v.z), __float2half_rn(v.w));
    ((__half2*)Wh)[2 * i]     = h0;
    ((__half2*)Wh)[2 * i + 1] = h1;
}

// ---------------- LayerNorm (+res), optional fp32 and fp16 hi/lo out ------
__global__ void __launch_bounds__(256) ln_kernel(
    const float* __restrict__ in, const float* __restrict__ res,
    const float* __restrict__ gam, const float* __restrict__ bet,
    float* __restrict__ outf, __half* __restrict__ outh, __half* __restrict__ outl)
{
    const int row = blockIdx.x, tid = threadIdx.x;
    const size_t base = (size_t)row * D_MODEL;
    float4 v = *(const float4*)(in + base + tid * 4);
    if (res) {
        float4 r = *(const float4*)(res + base + tid * 4);
        v.x += r.x; v.y += r.y; v.z += r.z; v.w += r.w;
    }
    float s  = v.x + v.y + v.z + v.w;
    float ss = v.x * v.x + v.y * v.y + v.z * v.z + v.w * v.w;
    #pragma unroll
    for (int o = 16; o > 0; o >>= 1) {
        s  += __shfl_down_sync(0xffffffffu, s,  o);
        ss += __shfl_down_sync(0xffffffffu, ss, o);
    }
    __shared__ float sh_s[8], sh_ss[8];
    const int w = tid >> 5, l = tid & 31;
    if (l == 0) { sh_s[w] = s; sh_ss[w] = ss; }
    __syncthreads();
    if (tid == 0) {
        float ts = 0.f, tss = 0.f;
        #pragma unroll
        for (int i = 0; i < 8; i++) { ts += sh_s[i]; tss += sh_ss[i]; }
        sh_s[0] = ts; sh_ss[0] = tss;
    }
    __syncthreads();
    const float mu  = sh_s[0] * (1.0f / D_MODEL);
    const float var = sh_ss[0] * (1.0f / D_MODEL) - mu * mu;
    const float inv = rsqrtf(var + 1e-6f);
    float4 g4 = *(const float4*)(gam + tid * 4);
    float4 b4 = *(const float4*)(bet + tid * 4);
    float4 o4;
    o4.x = (v.x - mu) * inv * g4.x + b4.x;
    o4.y = (v.y - mu) * inv * g4.y + b4.y;
    o4.z = (v.z - mu) * inv * g4.z + b4.z;
    o4.w = (v.w - mu) * inv * g4.w + b4.w;
    if (outf) *(float4*)(outf + base + tid * 4) = o4;
    if (outh) {
        __half2 h0, l0, h1, l1;
        split2h(o4.x, o4.y, &h0, &l0);
        split2h(o4.z, o4.w, &h1, &l1);
        *(__half2*)(outh + base + tid * 4)     = h0;
        *(__half2*)(outh + base + tid * 4 + 2) = h1;
        *(__half2*)(outl + base + tid * 4)     = l0;
        *(__half2*)(outl + base + tid * 4 + 2) = l1;
    }
}

// ---------------- per-token head-mixing attention (fp16 hi/lo out) --------
__global__ void __launch_bounds__(256) attn_kernel(
    const float* __restrict__ q, const float* __restrict__ k,
    const float* __restrict__ v, __half* __restrict__ oh, __half* __restrict__ ol)
{
    const int row = blockIdx.x, tid = threadIdx.x;
    __shared__ float sq[D_MODEL], sk[D_MODEL], sv[D_MODEL];
    __shared__ float sS[H_HEADS][H_HEADS + 1];
    const size_t base = (size_t)row * D_MODEL;
    ((float4*)sq)[tid] = *(const float4*)(q + base + tid * 4);
    ((float4*)sk)[tid] = *(const float4*)(k + base + tid * 4);
    ((float4*)sv)[tid] = *(const float4*)(v + base + tid * 4);
    __syncthreads();
    {
        const int h = tid >> 4, g = tid & 15;
        float s = 0.f;
        #pragma unroll
        for (int d = 0; d < DK; d++) s += sq[h * DK + d] * sk[g * DK + d];
        sS[h][g] = s * 0.125f;
    }
    __syncthreads();
    if (tid < H_HEADS) {
        float mx = -1e30f;
        #pragma unroll
        for (int g = 0; g < H_HEADS; g++) mx = fmaxf(mx, sS[tid][g]);
        float sum = 0.f;
        #pragma unroll
        for (int g = 0; g < H_HEADS; g++) {
            float e = expf(sS[tid][g] - mx);
            sS[tid][g] = e; sum += e;
        }
        const float invs = 1.0f / sum;
        #pragma unroll
        for (int g = 0; g < H_HEADS; g++) sS[tid][g] *= invs;
    }
    __syncthreads();
    const int b = row / T_SEQ, t = row % T_SEQ;
    const size_t ob = (size_t)b * T_SEQ * D_MODEL + (size_t)t * DK;
    #pragma unroll
    for (int i = 0; i < 4; i++) {
        const int idx = i * 256 + tid;
        const int h = idx >> 6, d = idx & 63;
        float acc = 0.f;
        #pragma unroll
        for (int g = 0; g < H_HEADS; g++) acc += sS[h][g] * sv[g * DK + d];
        const size_t off = ob + (size_t)h * T_SEQ * DK + d;
        __half hi = __float2half_rn(acc);
        oh[off] = hi;
        ol[off] = __float2half_rn(acc - __half2float(hi));
    }
}

// ---------------- fp16 2-product HMMA GEMM, 128x256 tile, 512 thr ---------
// C = (Ah+Al)[M,K] @ Bh[K,Nn], fp32 acc. 16 warps (2x8), warp tile 64x32.
// EPI: 0 fp32 out; 1 bias+GELU -> fp16 hi/lo out; 2 bias+res -> fp32 out
template<int EPI>
__global__ void __launch_bounds__(512, 1) hmma_gemm(
    const __half* __restrict__ Ah, const __half* __restrict__ Al,
    const __half* __restrict__ Bh,
    float* __restrict__ C, __half* __restrict__ Ch, __half* __restrict__ Cl,
    int K, int Nn, const float* __restrict__ bias, const float* __restrict__ res)
{
    extern __shared__ __align__(16) char sm[];
    const int tid = threadIdx.x, lane = tid & 31, wid = tid >> 5;
    const int bm = blockIdx.y, bn = blockIdx.x;
    const int wm = (wid >> 3) * 64;        // 0 or 64
    const int wn = (wid & 7) * 32;         // 0..224
    const uint32_t sb0 = smem_u32(sm);

    float acc[4][4][4];
    #pragma unroll
    for (int t = 0; t < 4; t++)
        #pragma unroll
        for (int j = 0; j < 4; j++)
            #pragma unroll
            for (int e = 0; e < 4; e++) acc[t][j][e] = 0.f;

    const int NK = K / 32;

    auto load_stage = [&](int i, int s) {
        const uint32_t st = sb0 + s * STAGE_B;
        const int k0 = i * 32;
        {   // A: 128 rows x 64B; 512 chunks; one h + one l per thread
            const int r = tid >> 2, c = tid & 3;
            const uint32_t dst = st + r * 64 + ((c ^ ((r >> 1) & 3)) << 4);
            const size_t src = (size_t)(bm * 128 + r) * K + k0 + c * 8;
            cp16(dst,        Ah + src);
            cp16(dst + 8192, Al + src);
        }
        #pragma unroll
        for (int j = 0; j < 2; j++) {   // Bh: 32 rows x 512B; 1024 chunks
            const int ci = tid + j * 512;
            const int r = ci >> 5, c = ci & 31;
            const uint32_t dst = st + 16384 + r * 512 + ((c ^ (r & 7)) << 4);
            const size_t src = (size_t)(k0 + r) * Nn + bn * 256 + c * 8;
            cp16(dst, Bh + src);
        }
    };

    load_stage(0, 0); cp_commit();
    if (NK > 1) load_stage(1, 1);
    cp_commit();

    for (int i = 0; i < NK; i++) {
        cp_wait<1>();
        __syncthreads();
        if (i + 2 < NK) load_stage(i + 2, (i + 2) % 3);
        cp_commit();

        const uint32_t st = sb0 + (i % 3) * STAGE_B;
        #pragma unroll
        for (int kk = 0; kk < 32; kk += 16) {
            uint32_t ah[4][4], al[4][4], bh[2][4];
            const int acol = (kk >> 3) + ((lane >> 4) & 1);
            #pragma unroll
            for (int t = 0; t < 4; t++) {
                const int r = wm + t * 16 + (lane & 15);
                const uint32_t ad = st + r * 64 + ((acol ^ ((r >> 1) & 3)) << 4);
                ldsm_x4(ah[t], ad);
                ldsm_x4(al[t], ad + 8192);
            }
            const int rk = kk + (lane & 15);
            #pragma unroll
            for (int u = 0; u < 2; u++) {
                const int cB = (wn + u * 16 + ((lane & 16) ? 8 : 0)) >> 3;
                const uint32_t bd = st + 16384 + rk * 512 + ((cB ^ (rk & 7)) << 4);
                ldsm_x4t(bh[u], bd);
            }
            // pass 1: Ah*Bh
            #pragma unroll
            for (int t = 0; t < 4; t++)
                #pragma unroll
                for (int j = 0; j < 4; j++)
                    mma16816(acc[t][j], ah[t], bh[j >> 1][(j & 1) * 2], bh[j >> 1][(j & 1) * 2 + 1]);
            // pass 2: Al*Bh
            #pragma unroll
            for (int t = 0; t < 4; t++)
                #pragma unroll
                for (int j = 0; j < 4; j++)
                    mma16816(acc[t][j], al[t], bh[j >> 1][(j & 1) * 2], bh[j >> 1][(j & 1) * 2 + 1]);
        }
    }

    // epilogue
    const int l4 = lane >> 2, l2 = (lane & 3) * 2;
    #pragma unroll
    for (int t = 0; t < 4; t++)
        #pragma unroll
        for (int j = 0; j < 4; j++) {
            const int r0 = bm * 128 + wm + t * 16 + l4;
            const int c0 = bn * 256 + wn + j * 8 + l2;
            #pragma unroll
            for (int half = 0; half < 2; half++) {
                const int r = r0 + half * 8;
                float v0 = acc[t][j][half * 2];
                float v1 = acc[t][j][half * 2 + 1];
                if (EPI == 1) {
                    v0 += bias[c0];     v1 += bias[c0 + 1];
                    v0 = 0.5f * v0 * (1.0f + erff(v0 * 0.70710678118654752f));
                    v1 = 0.5f * v1 * (1.0f + erff(v1 * 0.70710678118654752f));
                    __half2 h2, l2b;
                    split2h(v0, v1, &h2, &l2b);
                    *(__half2*)(Ch + (size_t)r * Nn + c0) = h2;
                    *(__half2*)(Cl + (size_t)r * Nn + c0) = l2b;
                } else {
                    if (EPI == 2) {
                        float2 rr = *(const float2*)(res + (size_t)r * Nn + c0);
                        v0 += bias[c0] + rr.x;
                        v1 += bias[c0 + 1] + rr.y;
                    }
                    *(float2*)(C + (size_t)r * Nn + c0) = make_float2(v0, v1);
                }
            }
        }
}

// ---------------- launch ----------------
extern "C" void kernel_launch(void* const* d_in, const int* in_sizes, int n_in,
                              void* d_out, int out_size)
{
    const float* x     = (const float*)d_in[0];
    const float* wq    = (const float*)d_in[1];
    const float* wk    = (const float*)d_in[2];
    const float* wv    = (const float*)d_in[3];
    const float* wo    = (const float*)d_in[4];
    const float* ln1g  = (const float*)d_in[5];
    const float* ln1b  = (const float*)d_in[6];
    const float* w1    = (const float*)d_in[7];
    const float* b1    = (const float*)d_in[8];
    const float* w2    = (const float*)d_in[9];
    const float* b2    = (const float*)d_in[10];
    const float* ln2g  = (const float*)d_in[11];
    const float* ln2b  = (const float*)d_in[12];
    float* out = (float*)d_out;

    float *q, *k, *v, *o2, *q2, *y;
    __half *x1h, *x1l, *osh, *osl, *q2h, *q2l, *hh, *hl;
    __half *wqh, *wkh, *wvh, *woh, *w1h, *w2h;
    cudaGetSymbolAddress((void**)&q,  g_q);
    cudaGetSymbolAddress((void**)&k,  g_k);
    cudaGetSymbolAddress((void**)&v,  g_v);
    cudaGetSymbolAddress((void**)&o2, g_o2);
    cudaGetSymbolAddress((void**)&q2, g_q2);
    cudaGetSymbolAddress((void**)&y,  g_y);
    cudaGetSymbolAddress((void**)&x1h, g_x1h);
    cudaGetSymbolAddress((void**)&x1l, g_x1l);
    cudaGetSymbolAddress((void**)&osh, g_osh);
    cudaGetSymbolAddress((void**)&osl, g_osl);
    cudaGetSymbolAddress((void**)&q2h, g_q2h);
    cudaGetSymbolAddress((void**)&q2l, g_q2l);
    cudaGetSymbolAddress((void**)&hh,  g_hh);
    cudaGetSymbolAddress((void**)&hl,  g_hl);
    cudaGetSymbolAddress((void**)&wqh, g_wqh);
    cudaGetSymbolAddress((void**)&wkh, g_wkh);
    cudaGetSymbolAddress((void**)&wvh, g_wvh);
    cudaGetSymbolAddress((void**)&woh, g_woh);
    cudaGetSymbolAddress((void**)&w1h, g_w1h);
    cudaGetSymbolAddress((void**)&w2h, g_w2h);

    cudaFuncSetAttribute(hmma_gemm<0>, cudaFuncAttributeMaxDynamicSharedMemorySize, GEMM_SMEM);
    cudaFuncSetAttribute(hmma_gemm<1>, cudaFuncAttributeMaxDynamicSharedMemorySize, GEMM_SMEM);
    cudaFuncSetAttribute(hmma_gemm<2>, cudaFuncAttributeMaxDynamicSharedMemorySize, GEMM_SMEM);

    const int nDD4 = D_MODEL * D_MODEL / 4;
    const int nDF4 = D_MODEL * D_FF / 4;
    convw_kernel<<<nDD4 / 256, 256>>>(wq, wqh, nDD4);
    convw_kernel<<<nDD4 / 256, 256>>>(wk, wkh, nDD4);
    convw_kernel<<<nDD4 / 256, 256>>>(wv, wvh, nDD4);
    convw_kernel<<<nDD4 / 256, 256>>>(wo, woh, nDD4);
    convw_kernel<<<nDF4 / 256, 256>>>(w1, w1h, nDF4);
    convw_kernel<<<nDF4 / 256, 256>>>(w2, w2h, nDF4);

    const dim3 gD(D_MODEL / 256, N_TOK / 128);   // (4, 128)
    const dim3 gF(D_FF    / 256, N_TOK / 128);   // (16, 128)

    ln_kernel<<<N_TOK, 256>>>(x, nullptr, ln1g, ln1b, nullptr, x1h, x1l);
    hmma_gemm<0><<<gD, 512, GEMM_SMEM>>>(x1h, x1l, wqh, q, nullptr, nullptr,
                                         D_MODEL, D_MODEL, nullptr, nullptr);
    hmma_gemm<0><<<gD, 512, GEMM_SMEM>>>(x1h, x1l, wkh, k, nullptr, nullptr,
                                         D_MODEL, D_MODEL, nullptr, nullptr);
    hmma_gemm<0><<<gD, 512, GEMM_SMEM>>>(x1h, x1l, wvh, v, nullptr, nullptr,
                                         D_MODEL, D_MODEL, nullptr, nullptr);
    attn_kernel<<<N_TOK, 256>>>(q, k, v, osh, osl);
    hmma_gemm<0><<<gD, 512, GEMM_SMEM>>>(osh, osl, woh, o2, nullptr, nullptr,
                                         D_MODEL, D_MODEL, nullptr, nullptr);
    ln_kernel<<<N_TOK, 256>>>(o2, x, ln1g, ln1b, q2, q2h, q2l);
    hmma_gemm<1><<<gF, 512, GEMM_SMEM>>>(q2h, q2l, w1h, nullptr, hh, hl,
                                         D_MODEL, D_FF, b1, nullptr);
    hmma_gemm<2><<<gD, 512, GEMM_SMEM>>>(hh, hl, w2h, y, nullptr, nullptr,
                                         D_FF, D_MODEL, b2, q2);
    ln_kernel<<<N_TOK, 256>>>(y, nullptr, ln2g, ln2b, out, nullptr, nullptr);
}

// round 13
// speedup vs baseline: 3.4401x; 1.0014x over previous
#include <cuda_runtime.h>
#include <cuda_fp16.h>
#include <math.h>
#include <stdint.h>

#define D_MODEL 1024
#define D_FF    4096
#define T_SEQ   4096
#define N_TOK   16384
#define H_HEADS 16
#define DK      64

#define STAGE_B   32768              // Ah 8K | Al 8K | Bh 16K
#define GEMM_SMEM (3 * STAGE_B)      // 96 KB, 3-stage pipeline

// ---------------- device scratch ----------------
__device__ float g_q [(size_t)N_TOK * D_MODEL];
__device__ float g_k [(size_t)N_TOK * D_MODEL];
__device__ float g_v [(size_t)N_TOK * D_MODEL];
__device__ float g_o2[(size_t)N_TOK * D_MODEL];
__device__ float g_q2[(size_t)N_TOK * D_MODEL];
__device__ float g_y [(size_t)N_TOK * D_MODEL];

__device__ __align__(16) __half g_x1h[(size_t)N_TOK * D_MODEL];
__device__ __align__(16) __half g_x1l[(size_t)N_TOK * D_MODEL];
__device__ __align__(16) __half g_osh[(size_t)N_TOK * D_MODEL];
__device__ __align__(16) __half g_osl[(size_t)N_TOK * D_MODEL];
__device__ __align__(16) __half g_q2h[(size_t)N_TOK * D_MODEL];
__device__ __align__(16) __half g_q2l[(size_t)N_TOK * D_MODEL];
__device__ __align__(16) __half g_hh [(size_t)N_TOK * D_FF];
__device__ __align__(16) __half g_hl [(size_t)N_TOK * D_FF];
__device__ __align__(16) __half g_wqh[(size_t)D_MODEL * D_MODEL];
__device__ __align__(16) __half g_wkh[(size_t)D_MODEL * D_MODEL];
__device__ __align__(16) __half g_wvh[(size_t)D_MODEL * D_MODEL];
__device__ __align__(16) __half g_woh[(size_t)D_MODEL * D_MODEL];
__device__ __align__(16) __half g_w1h[(size_t)D_MODEL * D_FF];
__device__ __align__(16) __half g_w2h[(size_t)D_FF * D_MODEL];

// ---------------- helpers ----------------
__device__ __forceinline__ uint32_t smem_u32(const void* p) {
    uint32_t a;
    asm("{ .reg .u64 t; cvta.to.shared.u64 t, %1; cvt.u32.u64 %0, t; }" : "=r"(a) : "l"(p));
    return a;
}
__device__ __forceinline__ void cp16(uint32_t dst, const void* src) {
    asm volatile("cp.async.cg.shared.global [%0], [%1], 16;" :: "r"(dst), "l"(src));
}
__device__ __forceinline__ void cp_commit() {
    asm volatile("cp.async.commit_group;" ::: "memory");
}
template<int N>
__device__ __forceinline__ void cp_wait() {
    asm volatile("cp.async.wait_group %0;" :: "n"(N) : "memory");
}
__device__ __forceinline__ void ldsm_x4(uint32_t* r, uint32_t a) {
    asm volatile("ldmatrix.sync.aligned.m8n8.x4.shared.b16 {%0,%1,%2,%3}, [%4];"
                 : "=r"(r[0]), "=r"(r[1]), "=r"(r[2]), "=r"(r[3]) : "r"(a));
}
__device__ __forceinline__ void ldsm_x4t(uint32_t* r, uint32_t a) {
    asm volatile("ldmatrix.sync.aligned.m8n8.x4.trans.shared.b16 {%0,%1,%2,%3}, [%4];"
                 : "=r"(r[0]), "=r"(r[1]), "=r"(r[2]), "=r"(r[3]) : "r"(a));
}
__device__ __forceinline__ void mma16816(float* d, const uint32_t* a, uint32_t b0, uint32_t b1) {
    asm volatile("mma.sync.aligned.m16n8k16.row.col.f32.f16.f16.f32 "
                 "{%0,%1,%2,%3}, {%4,%5,%6,%7}, {%8,%9}, {%0,%1,%2,%3};"
                 : "+f"(d[0]), "+f"(d[1]), "+f"(d[2]), "+f"(d[3])
                 : "r"(a[0]), "r"(a[1]), "r"(a[2]), "r"(a[3]), "r"(b0), "r"(b1));
}
__device__ __forceinline__ void split2h(float x, float y, __half2* h, __half2* l) {
    __half hx = __float2half_rn(x);
    __half hy = __float2half_rn(y);
    *h = __halves2half2(hx, hy);
    *l = __halves2half2(__float2half_rn(x - __half2float(hx)),
                        __float2half_rn(y - __half2float(hy)));
}

// ---------------- fp32 -> fp16 (weights: hi only) ----------------
__global__ void __launch_bounds__(256) convw_kernel(
    const float* __restrict__ W, __half* __restrict__ Wh, int n4)
{
    int i = blockIdx.x * 256 + threadIdx.x;
    if (i >= n4) return;
    float4 v = ((const float4*)W)[i];
    __half2 h0 = __halves2half2(__float2half_rn(v.x), __float2half_rn(v.y));
    __half2 h1 = __halves2half2(__float2half_rn(v.z), __float2half_rn(v.w));
    ((__half2*)Wh)[2 * i]     = h0;
    ((__half2*)Wh)[2 * i + 1] = h1;
}

// ---------------- LayerNorm (+res), optional fp32 and fp16 hi/lo out ------
__global__ void __launch_bounds__(256) ln_kernel(
    const float* __restrict__ in, const float* __restrict__ res,
    const float* __restrict__ gam, const float* __restrict__ bet,
    float* __restrict__ outf, __half* __restrict__ outh, __half* __restrict__ outl)
{
    const int row = blockIdx.x, tid = threadIdx.x;
    const size_t base = (size_t)row * D_MODEL;
    float4 v = *(const float4*)(in + base + tid * 4);
    if (res) {
        float4 r = *(const float4*)(res + base + tid * 4);
        v.x += r.x; v.y += r.y; v.z += r.z; v.w += r.w;
    }
    float s  = v.x + v.y + v.z + v.w;
    float ss = v.x * v.x + v.y * v.y + v.z * v.z + v.w * v.w;
    #pragma unroll
    for (int o = 16; o > 0; o >>= 1) {
        s  += __shfl_down_sync(0xffffffffu, s,  o);
        ss += __shfl_down_sync(0xffffffffu, ss, o);
    }
    __shared__ float sh_s[8], sh_ss[8];
    const int w = tid >> 5, l = tid & 31;
    if (l == 0) { sh_s[w] = s; sh_ss[w] = ss; }
    __syncthreads();
    if (tid == 0) {
        float ts = 0.f, tss = 0.f;
        #pragma unroll
        for (int i = 0; i < 8; i++) { ts += sh_s[i]; tss += sh_ss[i]; }
        sh_s[0] = ts; sh_ss[0] = tss;
    }
    __syncthreads();
    const float mu  = sh_s[0] * (1.0f / D_MODEL);
    const float var = sh_ss[0] * (1.0f / D_MODEL) - mu * mu;
    const float inv = rsqrtf(var + 1e-6f);
    float4 g4 = *(const float4*)(gam + tid * 4);
    float4 b4 = *(const float4*)(bet + tid * 4);
    float4 o4;
    o4.x = (v.x - mu) * inv * g4.x + b4.x;
    o4.y = (v.y - mu) * inv * g4.y + b4.y;
    o4.z = (v.z - mu) * inv * g4.z + b4.z;
    o4.w = (v.w - mu) * inv * g4.w + b4.w;
    if (outf) *(float4*)(outf + base + tid * 4) = o4;
    if (outh) {
        __half2 h0, l0, h1, l1;
        split2h(o4.x, o4.y, &h0, &l0);
        split2h(o4.z, o4.w, &h1, &l1);
        *(__half2*)(outh + base + tid * 4)     = h0;
        *(__half2*)(outh + base + tid * 4 + 2) = h1;
        *(__half2*)(outl + base + tid * 4)     = l0;
        *(__half2*)(outl + base + tid * 4 + 2) = l1;
    }
}

// ---------------- per-token head-mixing attention (fp16 hi/lo out) --------
__global__ void __launch_bounds__(256) attn_kernel(
    const float* __restrict__ q, const float* __restrict__ k,
    const float* __restrict__ v, __half* __restrict__ oh, __half* __restrict__ ol)
{
    const int row = blockIdx.x, tid = threadIdx.x;
    __shared__ float sq[D_MODEL], sk[D_MODEL], sv[D_MODEL];
    __shared__ float sS[H_HEADS][H_HEADS + 1];
    const size_t base = (size_t)row * D_MODEL;
    ((float4*)sq)[tid] = *(const float4*)(q + base + tid * 4);
    ((float4*)sk)[tid] = *(const float4*)(k + base + tid * 4);
    ((float4*)sv)[tid] = *(const float4*)(v + base + tid * 4);
    __syncthreads();
    {
        const int h = tid >> 4, g = tid & 15;
        float s = 0.f;
        #pragma unroll
        for (int d = 0; d < DK; d++) s += sq[h * DK + d] * sk[g * DK + d];
        sS[h][g] = s * 0.125f;
    }
    __syncthreads();
    if (tid < H_HEADS) {
        float mx = -1e30f;
        #pragma unroll
        for (int g = 0; g < H_HEADS; g++) mx = fmaxf(mx, sS[tid][g]);
        float sum = 0.f;
        #pragma unroll
        for (int g = 0; g < H_HEADS; g++) {
            float e = expf(sS[tid][g] - mx);
            sS[tid][g] = e; sum += e;
        }
        const float invs = 1.0f / sum;
        #pragma unroll
        for (int g = 0; g < H_HEADS; g++) sS[tid][g] *= invs;
    }
    __syncthreads();
    const int b = row / T_SEQ, t = row % T_SEQ;
    const size_t ob = (size_t)b * T_SEQ * D_MODEL + (size_t)t * DK;
    #pragma unroll
    for (int i = 0; i < 4; i++) {
        const int idx = i * 256 + tid;
        const int h = idx >> 6, d = idx & 63;
        float acc = 0.f;
        #pragma unroll
        for (int g = 0; g < H_HEADS; g++) acc += sS[h][g] * sv[g * DK + d];
        const size_t off = ob + (size_t)h * T_SEQ * DK + d;
        __half hi = __float2half_rn(acc);
        oh[off] = hi;
        ol[off] = __float2half_rn(acc - __half2float(hi));
    }
}

// ---------------- fp16 2-product HMMA GEMM, 128x256 tile, 512 thr ---------
// C = (Ah+Al)[M,K] @ Bh[K,Nn], fp32 acc. 16 warps (2x8), warp tile 64x32.
// EPI: 0 fp32 out; 1 bias+GELU -> fp16 hi/lo out; 2 bias+res -> fp32 out
template<int EPI>
__global__ void __launch_bounds__(512, 1) hmma_gemm(
    const __half* __restrict__ Ah, const __half* __restrict__ Al,
    const __half* __restrict__ Bh,
    float* __restrict__ C, __half* __restrict__ Ch, __half* __restrict__ Cl,
    int K, int Nn, const float* __restrict__ bias, const float* __restrict__ res)
{
    extern __shared__ __align__(16) char sm[];
    const int tid = threadIdx.x, lane = tid & 31, wid = tid >> 5;
    const int bm = blockIdx.y, bn = blockIdx.x;
    const int wm = (wid >> 3) * 64;        // 0 or 64
    const int wn = (wid & 7) * 32;         // 0..224
    const uint32_t sb0 = smem_u32(sm);

    float acc[4][4][4];
    #pragma unroll
    for (int t = 0; t < 4; t++)
        #pragma unroll
        for (int j = 0; j < 4; j++)
            #pragma unroll
            for (int e = 0; e < 4; e++) acc[t][j][e] = 0.f;

    const int NK = K / 32;

    auto load_stage = [&](int i, int s) {
        const uint32_t st = sb0 + s * STAGE_B;
        const int k0 = i * 32;
        {   // A: 128 rows x 64B; 512 chunks; one h + one l per thread
            const int r = tid >> 2, c = tid & 3;
            const uint32_t dst = st + r * 64 + ((c ^ ((r >> 1) & 3)) << 4);
            const size_t src = (size_t)(bm * 128 + r) * K + k0 + c * 8;
            cp16(dst,        Ah + src);
            cp16(dst + 8192, Al + src);
        }
        #pragma unroll
        for (int j = 0; j < 2; j++) {   // Bh: 32 rows x 512B; 1024 chunks
            const int ci = tid + j * 512;
            const int r = ci >> 5, c = ci & 31;
            const uint32_t dst = st + 16384 + r * 512 + ((c ^ (r & 7)) << 4);
            const size_t src = (size_t)(k0 + r) * Nn + bn * 256 + c * 8;
            cp16(dst, Bh + src);
        }
    };

    load_stage(0, 0); cp_commit();
    if (NK > 1) load_stage(1, 1);
    cp_commit();

    for (int i = 0; i < NK; i++) {
        cp_wait<1>();
        __syncthreads();
        if (i + 2 < NK) load_stage(i + 2, (i + 2) % 3);
        cp_commit();

        const uint32_t st = sb0 + (i % 3) * STAGE_B;
        #pragma unroll
        for (int kk = 0; kk < 32; kk += 16) {
            uint32_t ah[4][4], al[4][4], bh[2][4];
            const int acol = (kk >> 3) + ((lane >> 4) & 1);
            #pragma unroll
            for (int t = 0; t < 4; t++) {
                const int r = wm + t * 16 + (lane & 15);
                const uint32_t ad = st + r * 64 + ((acol ^ ((r >> 1) & 3)) << 4);
                ldsm_x4(ah[t], ad);
                ldsm_x4(al[t], ad + 8192);
            }
            const int rk = kk + (lane & 15);
            #pragma unroll
            for (int u = 0; u < 2; u++) {
                const int cB = (wn + u * 16 + ((lane & 16) ? 8 : 0)) >> 3;
                const uint32_t bd = st + 16384 + rk * 512 + ((cB ^ (rk & 7)) << 4);
                ldsm_x4t(bh[u], bd);
            }
            // pass 1: Ah*Bh
            #pragma unroll
            for (int t = 0; t < 4; t++)
                #pragma unroll
                for (int j = 0; j < 4; j++)
                    mma16816(acc[t][j], ah[t], bh[j >> 1][(j & 1) * 2], bh[j >> 1][(j & 1) * 2 + 1]);
            // pass 2: Al*Bh
            #pragma unroll
            for (int t = 0; t < 4; t++)
                #pragma unroll
                for (int j = 0; j < 4; j++)
                    mma16816(acc[t][j], al[t], bh[j >> 1][(j & 1) * 2], bh[j >> 1][(j & 1) * 2 + 1]);
        }
    }

    // epilogue
    const int l4 = lane >> 2, l2 = (lane & 3) * 2;
    #pragma unroll
    for (int t = 0; t < 4; t++)
        #pragma unroll
        for (int j = 0; j < 4; j++) {
            const int r0 = bm * 128 + wm + t * 16 + l4;
            const int c0 = bn * 256 + wn + j * 8 + l2;
            #pragma unroll
            for (int half = 0; half < 2; half++) {
                const int r = r0 + half * 8;
                float v0 = acc[t][j][half * 2];
                float v1 = acc[t][j][half * 2 + 1];
                if (EPI == 1) {
                    v0 += bias[c0];     v1 += bias[c0 + 1];
                    v0 = 0.5f * v0 * (1.0f + erff(v0 * 0.70710678118654752f));
                    v1 = 0.5f * v1 * (1.0f + erff(v1 * 0.70710678118654752f));
                    __half2 h2, l2b;
                    split2h(v0, v1, &h2, &l2b);
                    *(__half2*)(Ch + (size_t)r * Nn + c0) = h2;
                    *(__half2*)(Cl + (size_t)r * Nn + c0) = l2b;
                } else {
                    if (EPI == 2) {
                        float2 rr = *(const float2*)(res + (size_t)r * Nn + c0);
                        v0 += bias[c0] + rr.x;
                        v1 += bias[c0 + 1] + rr.y;
                    }
                    *(float2*)(C + (size_t)r * Nn + c0) = make_float2(v0, v1);
                }
            }
        }
}

// ---------------- launch ----------------
extern "C" void kernel_launch(void* const* d_in, const int* in_sizes, int n_in,
                              void* d_out, int out_size)
{
    const float* x     = (const float*)d_in[0];
    const float* wq    = (const float*)d_in[1];
    const float* wk    = (const float*)d_in[2];
    const float* wv    = (const float*)d_in[3];
    const float* wo    = (const float*)d_in[4];
    const float* ln1g  = (const float*)d_in[5];
    const float* ln1b  = (const float*)d_in[6];
    const float* w1    = (const float*)d_in[7];
    const float* b1    = (const float*)d_in[8];
    const float* w2    = (const float*)d_in[9];
    const float* b2    = (const float*)d_in[10];
    const float* ln2g  = (const float*)d_in[11];
    const float* ln2b  = (const float*)d_in[12];
    float* out = (float*)d_out;

    float *q, *k, *v, *o2, *q2, *y;
    __half *x1h, *x1l, *osh, *osl, *q2h, *q2l, *hh, *hl;
    __half *wqh, *wkh, *wvh, *woh, *w1h, *w2h;
    cudaGetSymbolAddress((void**)&q,  g_q);
    cudaGetSymbolAddress((void**)&k,  g_k);
    cudaGetSymbolAddress((void**)&v,  g_v);
    cudaGetSymbolAddress((void**)&o2, g_o2);
    cudaGetSymbolAddress((void**)&q2, g_q2);
    cudaGetSymbolAddress((void**)&y,  g_y);
    cudaGetSymbolAddress((void**)&x1h, g_x1h);
    cudaGetSymbolAddress((void**)&x1l, g_x1l);
    cudaGetSymbolAddress((void**)&osh, g_osh);
    cudaGetSymbolAddress((void**)&osl, g_osl);
    cudaGetSymbolAddress((void**)&q2h, g_q2h);
    cudaGetSymbolAddress((void**)&q2l, g_q2l);
    cudaGetSymbolAddress((void**)&hh,  g_hh);
    cudaGetSymbolAddress((void**)&hl,  g_hl);
    cudaGetSymbolAddress((void**)&wqh, g_wqh);
    cudaGetSymbolAddress((void**)&wkh, g_wkh);
    cudaGetSymbolAddress((void**)&wvh, g_wvh);
    cudaGetSymbolAddress((void**)&woh, g_woh);
    cudaGetSymbolAddress((void**)&w1h, g_w1h);
    cudaGetSymbolAddress((void**)&w2h, g_w2h);

    cudaFuncSetAttribute(hmma_gemm<0>, cudaFuncAttributeMaxDynamicSharedMemorySize, GEMM_SMEM);
    cudaFuncSetAttribute(hmma_gemm<1>, cudaFuncAttributeMaxDynamicSharedMemorySize, GEMM_SMEM);
    cudaFuncSetAttribute(hmma_gemm<2>, cudaFuncAttributeMaxDynamicSharedMemorySize, GEMM_SMEM);

    const int nDD4 = D_MODEL * D_MODEL / 4;
    const int nDF4 = D_MODEL * D_FF / 4;
    convw_kernel<<<nDD4 / 256, 256>>>(wq, wqh, nDD4);
    convw_kernel<<<nDD4 / 256, 256>>>(wk, wkh, nDD4);
    convw_kernel<<<nDD4 / 256, 256>>>(wv, wvh, nDD4);
    convw_kernel<<<nDD4 / 256, 256>>>(wo, woh, nDD4);
    convw_kernel<<<nDF4 / 256, 256>>>(w1, w1h, nDF4);
    convw_kernel<<<nDF4 / 256, 256>>>(w2, w2h, nDF4);

    const dim3 gD(D_MODEL / 256, N_TOK / 128);   // (4, 128)
    const dim3 gF(D_FF    / 256, N_TOK / 128);   // (16, 128)

    ln_kernel<<<N_TOK, 256>>>(x, nullptr, ln1g, ln1b, nullptr, x1h, x1l);
    hmma_gemm<0><<<gD, 512, GEMM_SMEM>>>(x1h, x1l, wqh, q, nullptr, nullptr,
                                         D_MODEL, D_MODEL, nullptr, nullptr);
    hmma_gemm<0><<<gD, 512, GEMM_SMEM>>>(x1h, x1l, wkh, k, nullptr, nullptr,
                                         D_MODEL, D_MODEL, nullptr, nullptr);
    hmma_gemm<0><<<gD, 512, GEMM_SMEM>>>(x1h, x1l, wvh, v, nullptr, nullptr,
                                         D_MODEL, D_MODEL, nullptr, nullptr);
    attn_kernel<<<N_TOK, 256>>>(q, k, v, osh, osl);
    hmma_gemm<0><<<gD, 512, GEMM_SMEM>>>(osh, osl, woh, o2, nullptr, nullptr,
                                         D_MODEL, D_MODEL, nullptr, nullptr);
    ln_kernel<<<N_TOK, 256>>>(o2, x, ln1g, ln1b, q2, q2h, q2l);
    hmma_gemm<1><<<gF, 512, GEMM_SMEM>>>(q2h, q2l, w1h, nullptr, hh, hl,
                                         D_MODEL, D_FF, b1, nullptr);
    hmma_gemm<2><<<gD, 512, GEMM_SMEM>>>(hh, hl, w2h, y, nullptr, nullptr,
                                         D_FF, D_MODEL, b2, q2);
    ln_kernel<<<N_TOK, 256>>>(y, nullptr, ln2g, ln2b, out, nullptr, nullptr);
}